// round 2
// baseline (speedup 1.0000x reference)
#include <cuda_runtime.h>
#include <math.h>

#define BSZ 4
#define SEQ 1024
#define DMODEL 512
#define NH 8
#define DHD 64
#define INNER_DIM 1536
#define MTOT (BSZ*SEQ)   /* 4096 */

#define AROWS 32
#define ATC 128
#define KVSTRIDE 65

// ---------------- scratch (device globals; no runtime allocation) ----------------
__device__ float g_q   [MTOT*DMODEL];
__device__ float g_kv  [MTOT*2*DMODEL];
__device__ float g_o   [MTOT*DMODEL];
__device__ float g_att [MTOT*DMODEL];
__device__ float g_h   [MTOT*DMODEL];
__device__ float g_u1  [MTOT*INNER_DIM];
__device__ float g_u2  [MTOT*INNER_DIM];
__device__ float g_gate[MTOT*INNER_DIM];
__device__ float g_ffn [MTOT*DMODEL];
__device__ float g_y   [MTOT*DMODEL];
__device__ float g_psum[BSZ*32*DMODEL];
__device__ float g_psq [BSZ*32*DMODEL];
__device__ float g_mean[BSZ*DMODEL];
__device__ float g_rstd[BSZ*DMODEL];

// ---------------- helpers ----------------
__device__ __forceinline__ unsigned f2key(float f) {
    unsigned u = __float_as_uint(f);
    return (u & 0x80000000u) ? ~u : (u | 0x80000000u);
}
__device__ __forceinline__ float key2f(unsigned k) {
    unsigned u = (k & 0x80000000u) ? (k & 0x7fffffffu) : ~k;
    return __uint_as_float(u);
}
__device__ __forceinline__ float warpMax(float v) {
    #pragma unroll
    for (int o = 16; o; o >>= 1) v = fmaxf(v, __shfl_xor_sync(0xffffffffu, v, o));
    return v;
}
__device__ __forceinline__ float warpSum(float v) {
    #pragma unroll
    for (int o = 16; o; o >>= 1) v += __shfl_xor_sync(0xffffffffu, v, o);
    return v;
}

// ---------------- generic fp32 GEMM: C[M,N] = A[M,K] @ B[K,N] (+bias[n]) ----------------
// Requires M%128==0, N%128==0, K%16==0 (true for all calls here).
__global__ __launch_bounds__(256) void sgemm_kernel(
    const float* __restrict__ A, const float* __restrict__ B,
    const float* __restrict__ bias, float* __restrict__ C,
    int M, int N, int K)
{
    __shared__ float As[16][132];
    __shared__ float Bs[16][128];
    const int bm = blockIdx.y * 128, bn = blockIdx.x * 128;
    const int tid = threadIdx.x;
    const int tx = tid & 15, ty = tid >> 4;
    const int arow = tid >> 2, acol = (tid & 3) << 2;
    const int brow = tid >> 5, bcol = (tid & 31) << 2;

    float acc[8][8];
    #pragma unroll
    for (int i = 0; i < 8; ++i)
        #pragma unroll
        for (int j = 0; j < 8; ++j) acc[i][j] = 0.0f;

    for (int k0 = 0; k0 < K; k0 += 16) {
        #pragma unroll
        for (int hh = 0; hh < 2; ++hh) {
            int r = arow + hh*64;
            float4 a = *(const float4*)(A + (size_t)(bm + r)*K + k0 + acol);
            As[acol+0][r] = a.x; As[acol+1][r] = a.y;
            As[acol+2][r] = a.z; As[acol+3][r] = a.w;
        }
        #pragma unroll
        for (int hh = 0; hh < 2; ++hh) {
            int r = brow + hh*8;
            *(float4*)(&Bs[r][bcol]) = *(const float4*)(B + (size_t)(k0 + r)*N + bn + bcol);
        }
        __syncthreads();
        #pragma unroll
        for (int kk = 0; kk < 16; ++kk) {
            float ra[8], rb[8];
            *(float4*)(ra)   = *(const float4*)(&As[kk][ty*8]);
            *(float4*)(ra+4) = *(const float4*)(&As[kk][ty*8+4]);
            *(float4*)(rb)   = *(const float4*)(&Bs[kk][tx*8]);
            *(float4*)(rb+4) = *(const float4*)(&Bs[kk][tx*8+4]);
            #pragma unroll
            for (int i = 0; i < 8; ++i)
                #pragma unroll
                for (int j = 0; j < 8; ++j)
                    acc[i][j] += ra[i]*rb[j];
        }
        __syncthreads();
    }

    float bv[8];
    #pragma unroll
    for (int j = 0; j < 8; ++j) bv[j] = bias ? bias[bn + tx*8 + j] : 0.0f;
    #pragma unroll
    for (int i = 0; i < 8; ++i) {
        float* cp = C + (size_t)(bm + ty*8 + i)*N + bn + tx*8;
        float4 v0 = make_float4(acc[i][0]+bv[0], acc[i][1]+bv[1], acc[i][2]+bv[2], acc[i][3]+bv[3]);
        float4 v1 = make_float4(acc[i][4]+bv[4], acc[i][5]+bv[5], acc[i][6]+bv[6], acc[i][7]+bv[7]);
        *(float4*)cp = v0; *(float4*)(cp+4) = v1;
    }
}

// ---------------- fused sparse attention ----------------
// grid: (SEQ/AROWS, BSZ*NH), 256 threads (8 warps, 4 rows/warp)
__global__ __launch_bounds__(256) void attn_kernel(
    const float* __restrict__ qb, const float* __restrict__ kvb, float* __restrict__ ob)
{
    extern __shared__ float sm[];
    float* sc  = sm;                          // AROWS*SEQ
    float* skv = sc + AROWS*SEQ;              // ATC*KVSTRIDE
    float* sq  = skv + ATC*KVSTRIDE;          // AROWS*DHD
    int*   hist = (int*)(sq + AROWS*DHD);     // 8*256

    const int tid = threadIdx.x, lane = tid & 31, wid = tid >> 5;
    const int b = blockIdx.y >> 3, h = blockIdx.y & 7;
    const int row0 = blockIdx.x * AROWS;
    const int r0 = wid * 4;

    // ---- load Q tile (32x64) ----
    {
        int e = tid * 8;
        int r = e >> 6, dh = e & 63;
        const float* src = qb + ((size_t)(b*SEQ + row0 + r))*DMODEL + h*DHD + dh;
        float4 v0 = *(const float4*)src;
        float4 v1 = *(const float4*)(src + 4);
        *(float4*)(sq + r*DHD + dh)     = v0;
        *(float4*)(sq + r*DHD + dh + 4) = v1;
    }

    // ---- scores: sc[r][t] = q_r . k_t / 8 ----
    for (int c = 0; c < SEQ/ATC; ++c) {
        __syncthreads();
        #pragma unroll
        for (int j = 0; j < 8; ++j) {
            int idx4 = tid + j*256;
            int t = idx4 >> 4;
            int kk = (idx4 & 15) << 2;
            const float* src = kvb + ((size_t)(b*SEQ + c*ATC + t))*(2*DMODEL) + h*DHD + kk;
            float4 v = *(const float4*)src;
            float* d = skv + t*KVSTRIDE + kk;
            d[0]=v.x; d[1]=v.y; d[2]=v.z; d[3]=v.w;
        }
        __syncthreads();
        const float* q0 = sq + (r0+0)*DHD;
        const float* q1 = sq + (r0+1)*DHD;
        const float* q2 = sq + (r0+2)*DHD;
        const float* q3 = sq + (r0+3)*DHD;
        #pragma unroll
        for (int tl = 0; tl < 4; ++tl) {
            int t = tl*32 + lane;
            const float* kp = skv + t*KVSTRIDE;
            float a0=0.f, a1=0.f, a2=0.f, a3=0.f;
            #pragma unroll 16
            for (int kk = 0; kk < DHD; ++kk) {
                float kvv = kp[kk];
                a0 += kvv*q0[kk]; a1 += kvv*q1[kk];
                a2 += kvv*q2[kk]; a3 += kvv*q3[kk];
            }
            int tg = c*ATC + t;
            sc[(r0+0)*SEQ+tg] = a0*0.125f;
            sc[(r0+1)*SEQ+tg] = a1*0.125f;
            sc[(r0+2)*SEQ+tg] = a2*0.125f;
            sc[(r0+3)*SEQ+tg] = a3*0.125f;
        }
    }

    // ---- per-row softmax + top-512 select + coefficient rewrite ----
    float invZ2[4];
    int* whist = hist + wid*256;
    for (int rr = 0; rr < 4; ++rr) {
        float* row = sc + (size_t)(r0+rr)*SEQ;

        float m = -3.4e38f;
        for (int t = lane; t < SEQ; t += 32) m = fmaxf(m, row[t]);
        m = warpMax(m);
        float z1 = 0.f;
        for (int t = lane; t < SEQ; t += 32) z1 += __expf(row[t] - m);
        z1 = warpSum(z1);
        float invZ1 = 1.0f / z1;

        // MSB radix select: 512th largest score
        unsigned prefix = 0;
        int k = SEQ/2;
        #pragma unroll
        for (int shift = 24; shift >= 0; shift -= 8) {
            unsigned mask = (shift < 24) ? (0xffffffffu << (shift + 8)) : 0u;
            for (int i = lane; i < 256; i += 32) whist[i] = 0;
            __syncwarp();
            for (int t = lane; t < SEQ; t += 32) {
                unsigned key = f2key(row[t]);
                if (((key ^ prefix) & mask) == 0)
                    atomicAdd(&whist[(key >> shift) & 255], 1);
            }
            __syncwarp();
            int sel = 0, newk = k;
            if (lane == 0) {
                int csum = 0;
                for (int bin = 255; bin >= 0; --bin) {
                    int hc = whist[bin];
                    if (csum + hc >= k) { sel = bin; newk = k - csum; break; }
                    csum += hc;
                }
            }
            sel = __shfl_sync(0xffffffffu, sel, 0);
            k   = __shfl_sync(0xffffffffu, newk, 0);
            prefix |= ((unsigned)sel) << shift;
            __syncwarp();
        }
        const unsigned tauKey = prefix;
        const int needEq = k;   // #elements equal to tau kept (earliest indices, jax tie rule)

        if (lane == 0) whist[0] = 0;
        __syncwarp();
        float z2l = 0.f;
        for (int t = lane; t < SEQ; t += 32) {
            float s = row[t];
            unsigned key = f2key(s);
            float coef = 1.0f;
            if (key > tauKey) {
                coef = __expf(__expf(s - m) * invZ1);
            } else if (key == tauKey) {
                int p = atomicAdd(&whist[0], 1);
                if (p < 255) whist[1 + p] = t;
            }
            row[t] = coef;
            z2l += coef;
        }
        __syncwarp();
        float z2 = warpSum(z2l);
        int neq = whist[0];
        float stau = key2f(tauKey);
        float ctau = __expf(__expf(stau - m) * invZ1);
        int listN = neq < 255 ? neq : 255;
        for (int i = lane; i < listN; i += 32) {
            int t = whist[1 + i];
            int rank = 0;
            for (int j = 0; j < listN; ++j) rank += (whist[1 + j] < t);
            if (rank < needEq) row[t] = ctau;
        }
        int keptEq = needEq < neq ? needEq : neq;
        z2 += (ctau - 1.0f) * (float)keptEq;
        invZ2[rr] = 1.0f / z2;
        __syncwarp();
    }

    // ---- AV: o_r = (1/Z2) * sum_t coef_t * v_t ----
    float o00=0.f,o01=0.f,o10=0.f,o11=0.f,o20=0.f,o21=0.f,o30=0.f,o31=0.f;
    for (int c = 0; c < SEQ/ATC; ++c) {
        __syncthreads();
        #pragma unroll
        for (int j = 0; j < 8; ++j) {
            int idx4 = tid + j*256;
            int t = idx4 >> 4;
            int kk = (idx4 & 15) << 2;
            const float* src = kvb + ((size_t)(b*SEQ + c*ATC + t))*(2*DMODEL) + DMODEL + h*DHD + kk;
            float4 v = *(const float4*)src;
            float* d = skv + t*KVSTRIDE + kk;
            d[0]=v.x; d[1]=v.y; d[2]=v.z; d[3]=v.w;
        }
        __syncthreads();
        const float* c0p = sc + (size_t)(r0+0)*SEQ + c*ATC;
        const float* c1p = sc + (size_t)(r0+1)*SEQ + c*ATC;
        const float* c2p = sc + (size_t)(r0+2)*SEQ + c*ATC;
        const float* c3p = sc + (size_t)(r0+3)*SEQ + c*ATC;
        #pragma unroll 4
        for (int t = 0; t < ATC; ++t) {
            float v0 = skv[t*KVSTRIDE + lane];
            float v1 = skv[t*KVSTRIDE + lane + 32];
            float w0 = c0p[t], w1 = c1p[t], w2 = c2p[t], w3 = c3p[t];
            o00 += w0*v0; o01 += w0*v1;
            o10 += w1*v0; o11 += w1*v1;
            o20 += w2*v0; o21 += w2*v1;
            o30 += w3*v0; o31 += w3*v1;
        }
    }
    {
        size_t base = ((size_t)(b*SEQ + row0 + r0))*DMODEL + h*DHD;
        ob[base + 0*DMODEL + lane]      = o00*invZ2[0];
        ob[base + 0*DMODEL + lane + 32] = o01*invZ2[0];
        ob[base + 1*DMODEL + lane]      = o10*invZ2[1];
        ob[base + 1*DMODEL + lane + 32] = o11*invZ2[1];
        ob[base + 2*DMODEL + lane]      = o20*invZ2[2];
        ob[base + 2*DMODEL + lane + 32] = o21*invZ2[2];
        ob[base + 3*DMODEL + lane]      = o30*invZ2[3];
        ob[base + 3*DMODEL + lane + 32] = o31*invZ2[3];
    }
}

// ---------------- residual + RMSNorm (per row of 512) ----------------
__global__ __launch_bounds__(128) void rms_add_kernel(
    const float* __restrict__ x, const float* __restrict__ a,
    const float* __restrict__ w, float* __restrict__ out)
{
    __shared__ float red[4];
    int row = blockIdx.x;
    int t = threadIdx.x;
    const float4* x4 = (const float4*)(x + (size_t)row*DMODEL);
    const float4* a4 = (const float4*)(a + (size_t)row*DMODEL);
    float4 xv = x4[t], av = a4[t];
    float4 s = make_float4(xv.x+av.x, xv.y+av.y, xv.z+av.z, xv.w+av.w);
    float ss = s.x*s.x + s.y*s.y + s.z*s.z + s.w*s.w;
    ss = warpSum(ss);
    if ((t & 31) == 0) red[t >> 5] = ss;
    __syncthreads();
    float tot = red[0] + red[1] + red[2] + red[3];
    float inv = rsqrtf(tot * (1.0f/DMODEL) + 1e-6f);
    float4 wv = ((const float4*)w)[t];
    float4 o = make_float4(s.x*inv*wv.x, s.y*inv*wv.y, s.z*inv*wv.z, s.w*inv*wv.w);
    ((float4*)(out + (size_t)row*DMODEL))[t] = o;
}

// ---------------- silu(u1)*u2 ----------------
__global__ void silu_mul_kernel(const float* __restrict__ u1, const float* __restrict__ u2,
                                float* __restrict__ g, int n4)
{
    int i = blockIdx.x*blockDim.x + threadIdx.x;
    if (i < n4) {
        float4 a = ((const float4*)u1)[i];
        float4 bb = ((const float4*)u2)[i];
        float4 r;
        r.x = a.x / (1.f + __expf(-a.x)) * bb.x;
        r.y = a.y / (1.f + __expf(-a.y)) * bb.y;
        r.z = a.z / (1.f + __expf(-a.z)) * bb.z;
        r.w = a.w / (1.f + __expf(-a.w)) * bb.w;
        ((float4*)g)[i] = r;
    }
}

// ---------------- instance norm over sequence dim ----------------
__global__ __launch_bounds__(256) void in1_kernel(
    const float* __restrict__ hh, const float* __restrict__ ffn,
    float* __restrict__ y, float* __restrict__ psum, float* __restrict__ psq)
{
    int b = blockIdx.y, chunk = blockIdx.x;
    int s0 = chunk * 32;
    int t = threadIdx.x;
    float s_[2] = {0.f, 0.f}, q_[2] = {0.f, 0.f};
    for (int s = 0; s < 32; ++s) {
        size_t base = ((size_t)(b*SEQ + s0 + s))*DMODEL;
        #pragma unroll
        for (int u = 0; u < 2; ++u) {
            int d = t + u*256;
            float yv = hh[base + d] + ffn[base + d];
            y[base + d] = yv;
            s_[u] += yv; q_[u] += yv*yv;
        }
    }
    #pragma unroll
    for (int u = 0; u < 2; ++u) {
        size_t pidx = ((size_t)b*32 + chunk)*DMODEL + t + u*256;
        psum[pidx] = s_[u];
        psq [pidx] = q_[u];
    }
}

__global__ void in2_kernel(const float* __restrict__ psum, const float* __restrict__ psq,
                           float* __restrict__ mean, float* __restrict__ rstd)
{
    int b = blockIdx.x, d = threadIdx.x;
    float s = 0.f, q = 0.f;
    for (int c = 0; c < 32; ++c) {
        size_t pidx = ((size_t)b*32 + c)*DMODEL + d;
        s += psum[pidx]; q += psq[pidx];
    }
    float m = s * (1.0f/SEQ);
    float v = q * (1.0f/SEQ) - m*m;
    mean[b*DMODEL + d] = m;
    rstd[b*DMODEL + d] = rsqrtf(v + 1e-5f);
}

__global__ void in3_kernel(const float* __restrict__ y, const float* __restrict__ mean,
                           const float* __restrict__ rstd, const float* __restrict__ w,
                           const float* __restrict__ bb, float* __restrict__ out)
{
    int i = blockIdx.x*blockDim.x + threadIdx.x;
    if (i < MTOT*DMODEL) {
        int d = i & (DMODEL - 1);
        int b = i >> 19;  // SEQ*DMODEL = 2^19
        float m = mean[b*DMODEL + d], r = rstd[b*DMODEL + d];
        out[i] = (y[i] - m) * r * w[d] + bb[d];
    }
}

// ---------------- launch ----------------
extern "C" void kernel_launch(void* const* d_in, const int* in_sizes, int n_in,
                              void* d_out, int out_size)
{
    (void)in_sizes; (void)n_in; (void)out_size;
    const float* x    = (const float*)d_in[0];
    const float* Wq   = (const float*)d_in[1];
    const float* bq   = (const float*)d_in[2];
    const float* Wkv  = (const float*)d_in[3];
    const float* bkv  = (const float*)d_in[4];
    const float* Wo   = (const float*)d_in[5];
    const float* bo   = (const float*)d_in[6];
    const float* rmsw = (const float*)d_in[7];
    const float* l1   = (const float*)d_in[8];
    const float* l2   = (const float*)d_in[9];
    const float* l3   = (const float*)d_in[10];
    const float* inw  = (const float*)d_in[11];
    const float* inb  = (const float*)d_in[12];
    float* out = (float*)d_out;

    float *q, *kv, *o, *att, *hbuf, *u1, *u2, *gate, *ffn, *y, *ps, *pq, *mn, *rs;
    cudaGetSymbolAddress((void**)&q,    g_q);
    cudaGetSymbolAddress((void**)&kv,   g_kv);
    cudaGetSymbolAddress((void**)&o,    g_o);
    cudaGetSymbolAddress((void**)&att,  g_att);
    cudaGetSymbolAddress((void**)&hbuf, g_h);
    cudaGetSymbolAddress((void**)&u1,   g_u1);
    cudaGetSymbolAddress((void**)&u2,   g_u2);
    cudaGetSymbolAddress((void**)&gate, g_gate);
    cudaGetSymbolAddress((void**)&ffn,  g_ffn);
    cudaGetSymbolAddress((void**)&y,    g_y);
    cudaGetSymbolAddress((void**)&ps,   g_psum);
    cudaGetSymbolAddress((void**)&pq,   g_psq);
    cudaGetSymbolAddress((void**)&mn,   g_mean);
    cudaGetSymbolAddress((void**)&rs,   g_rstd);

    const int smemBytes = (AROWS*SEQ + ATC*KVSTRIDE + AROWS*DHD + 8*256) * 4;
    cudaFuncSetAttribute(attn_kernel, cudaFuncAttributeMaxDynamicSharedMemorySize, smemBytes);

    // QKV projections
    sgemm_kernel<<<dim3(DMODEL/128,  MTOT/128), 256>>>(x, Wq,  bq,  q,  MTOT, DMODEL,   DMODEL);
    sgemm_kernel<<<dim3(2*DMODEL/128,MTOT/128), 256>>>(x, Wkv, bkv, kv, MTOT, 2*DMODEL, DMODEL);

    // sparse attention
    attn_kernel<<<dim3(SEQ/AROWS, BSZ*NH), 256, smemBytes>>>(q, kv, o);

    // output projection + residual + rmsnorm
    sgemm_kernel<<<dim3(DMODEL/128, MTOT/128), 256>>>(o, Wo, bo, att, MTOT, DMODEL, DMODEL);
    rms_add_kernel<<<MTOT, 128>>>(x, att, rmsw, hbuf);

    // SwiGLU FFN
    sgemm_kernel<<<dim3(INNER_DIM/128, MTOT/128), 256>>>(hbuf, l1, nullptr, u1, MTOT, INNER_DIM, DMODEL);
    sgemm_kernel<<<dim3(INNER_DIM/128, MTOT/128), 256>>>(hbuf, l2, nullptr, u2, MTOT, INNER_DIM, DMODEL);
    silu_mul_kernel<<<(MTOT*INNER_DIM/4 + 255)/256, 256>>>(u1, u2, gate, MTOT*INNER_DIM/4);
    sgemm_kernel<<<dim3(DMODEL/128, MTOT/128), 256>>>(gate, l3, nullptr, ffn, MTOT, DMODEL, INNER_DIM);

    // instance norm over sequence
    in1_kernel<<<dim3(32, BSZ), 256>>>(hbuf, ffn, y, ps, pq);
    in2_kernel<<<BSZ, DMODEL>>>(ps, pq, mn, rs);
    in3_kernel<<<(MTOT*DMODEL + 255)/256, 256>>>(y, mn, rs, inw, inb, out);
}

// round 4
// speedup vs baseline: 3.1900x; 3.1900x over previous
#include <cuda_runtime.h>
#include <math.h>

#define BSZ 4
#define SEQ 1024
#define DMODEL 512
#define NH 8
#define DHD 64
#define INNER_DIM 1536
#define MTOT (BSZ*SEQ)   /* 4096 */

#define AROWS 32
#define ATC 128
#define KVSTRIDE 68      /* 16B-aligned rows, conflict-free */

// ---------------- scratch (device globals; no runtime allocation) ----------------
__device__ float g_q   [MTOT*DMODEL];
__device__ float g_kv  [MTOT*2*DMODEL];
__device__ float g_o   [MTOT*DMODEL];
__device__ float g_att [MTOT*DMODEL];
__device__ float g_h   [MTOT*DMODEL];
__device__ float g_u1  [MTOT*INNER_DIM];
__device__ float g_u2  [MTOT*INNER_DIM];
__device__ float g_gate[MTOT*INNER_DIM];
__device__ float g_ffn [MTOT*DMODEL];
__device__ float g_y   [MTOT*DMODEL];
__device__ float g_psum[BSZ*32*DMODEL];
__device__ float g_psq [BSZ*32*DMODEL];
__device__ float g_mean[BSZ*DMODEL];
__device__ float g_rstd[BSZ*DMODEL];

// ---------------- helpers ----------------
__device__ __forceinline__ unsigned f2key(float f) {
    unsigned u = __float_as_uint(f);
    return (u & 0x80000000u) ? ~u : (u | 0x80000000u);
}
__device__ __forceinline__ float key2f(unsigned k) {
    unsigned u = (k & 0x80000000u) ? (k & 0x7fffffffu) : ~k;
    return __uint_as_float(u);
}
__device__ __forceinline__ float warpMax(float v) {
    #pragma unroll
    for (int o = 16; o; o >>= 1) v = fmaxf(v, __shfl_xor_sync(0xffffffffu, v, o));
    return v;
}
__device__ __forceinline__ float warpSum(float v) {
    #pragma unroll
    for (int o = 16; o; o >>= 1) v += __shfl_xor_sync(0xffffffffu, v, o);
    return v;
}
__device__ __forceinline__ unsigned to_tf32(float x) {
    unsigned u;
    asm("cvt.rna.tf32.f32 %0, %1;" : "=r"(u) : "f"(x));
    return u;
}
__device__ __forceinline__ float4 to_tf32x4(float4 v) {
    float4 r;
    r.x = __uint_as_float(to_tf32(v.x));
    r.y = __uint_as_float(to_tf32(v.y));
    r.z = __uint_as_float(to_tf32(v.z));
    r.w = __uint_as_float(to_tf32(v.w));
    return r;
}
__device__ __forceinline__ void ldsm4(unsigned* r, unsigned saddr) {
    asm volatile("ldmatrix.sync.aligned.m8n8.x4.shared.b16 {%0,%1,%2,%3}, [%4];"
                 : "=r"(r[0]), "=r"(r[1]), "=r"(r[2]), "=r"(r[3]) : "r"(saddr));
}
__device__ __forceinline__ void mma_tf32(float* d, const unsigned* a, const unsigned* b) {
    asm volatile(
        "mma.sync.aligned.m16n8k8.row.col.f32.tf32.tf32.f32 "
        "{%0,%1,%2,%3}, {%4,%5,%6,%7}, {%8,%9}, {%0,%1,%2,%3};"
        : "+f"(d[0]), "+f"(d[1]), "+f"(d[2]), "+f"(d[3])
        : "r"(a[0]), "r"(a[1]), "r"(a[2]), "r"(a[3]), "r"(b[0]), "r"(b[1]));
}

// ---------------- TF32 tensor-core GEMM: C[M,N] = A[M,K] @ B[K,N] (+bias) ----------------
// Requires M%128==0, N%128==0, K%32==0 (all calls satisfy this).
// Block 128x128, BK=32, 256 threads = 8 warps (2 along M x 4 along N), warp tile 64x32.
#define GBK 32
#define A_BUF_F32 4096           /* 128*32 */
#define B_STRIDE 136             /* 128 + 8 pad: conflict-free b-frag reads */
#define B_BUF_F32 (GBK*B_STRIDE) /* 4352 */

__global__ __launch_bounds__(256) void tf32gemm_kernel(
    const float* __restrict__ A, const float* __restrict__ B,
    const float* __restrict__ bias, float* __restrict__ C,
    int M, int N, int K)
{
    extern __shared__ float gsm[];
    float* AsF = gsm;                    // 2 * 4096
    float* BsF = gsm + 2*A_BUF_F32;      // 2 * 4352
    const unsigned asBase = (unsigned)__cvta_generic_to_shared(AsF);

    const int tid = threadIdx.x, lane = tid & 31, wid = tid >> 5;
    const int warpM = wid & 1, warpN = wid >> 1;
    const int bm = blockIdx.y * 128, bn = blockIdx.x * 128;

    // A fragment (ldmatrix) per-lane geometry
    const int mbase = warpM*64 + ((lane>>3)&1)*8 + (lane&7);
    const int jhi   = lane >> 4;        // 0/1: selects k4 within kstep
    const int xorv  = lane & 7;
    // B fragment per-lane geometry
    const int kb    = lane & 3;
    const int nbase = warpN*32 + (lane>>2);

    float acc[4][4][4];
    #pragma unroll
    for (int mt = 0; mt < 4; ++mt)
        #pragma unroll
        for (int nt = 0; nt < 4; ++nt)
            #pragma unroll
            for (int i = 0; i < 4; ++i) acc[mt][nt][i] = 0.0f;

    const int am = tid >> 3, ak4 = tid & 7;       // A staging: rows am+32p, 16B chunk ak4
    const int bk = tid >> 5, bn4 = tid & 31;      // B staging: rows bk+8p, float4 col bn4

    float4 regA[4], regB[4];
    // prologue load k0=0
    #pragma unroll
    for (int p = 0; p < 4; ++p)
        regA[p] = *(const float4*)(A + (size_t)(bm + am + p*32)*K + ak4*4);
    #pragma unroll
    for (int p = 0; p < 4; ++p)
        regB[p] = *(const float4*)(B + (size_t)(bk + p*8)*N + bn + bn4*4);
    #pragma unroll
    for (int p = 0; p < 4; ++p) {
        int m = am + p*32;
        int unit = m*8 + (ak4 ^ (m & 7));
        *(float4*)(AsF + unit*4) = to_tf32x4(regA[p]);
    }
    #pragma unroll
    for (int p = 0; p < 4; ++p)
        *(float4*)(BsF + (bk + p*8)*B_STRIDE + bn4*4) = to_tf32x4(regB[p]);
    __syncthreads();

    const int nIter = K / GBK;
    int buf = 0;
    for (int kt = 0; kt < nIter; ++kt) {
        bool more = (kt + 1 < nIter);
        if (more) {
            int k0 = (kt+1)*GBK;
            #pragma unroll
            for (int p = 0; p < 4; ++p)
                regA[p] = *(const float4*)(A + (size_t)(bm + am + p*32)*K + k0 + ak4*4);
            #pragma unroll
            for (int p = 0; p < 4; ++p)
                regB[p] = *(const float4*)(B + (size_t)(k0 + bk + p*8)*N + bn + bn4*4);
        }

        const unsigned aBufBase = asBase + buf*(A_BUF_F32*4);
        const float* bb = BsF + buf*B_BUF_F32;
        #pragma unroll
        for (int ks = 0; ks < 4; ++ks) {
            unsigned af[4][4];
            #pragma unroll
            for (int mt = 0; mt < 4; ++mt) {
                int m = mbase + mt*16;
                int unit = m*8 + ((ks*2 + jhi) ^ xorv);
                ldsm4(af[mt], aBufBase + unit*16);
            }
            unsigned bf[4][2];
            #pragma unroll
            for (int nt = 0; nt < 4; ++nt) {
                bf[nt][0] = __float_as_uint(bb[(ks*8 + kb    )*B_STRIDE + nbase + nt*8]);
                bf[nt][1] = __float_as_uint(bb[(ks*8 + kb + 4)*B_STRIDE + nbase + nt*8]);
            }
            #pragma unroll
            for (int mt = 0; mt < 4; ++mt)
                #pragma unroll
                for (int nt = 0; nt < 4; ++nt)
                    mma_tf32(acc[mt][nt], af[mt], bf[nt]);
        }

        if (more) {
            int nb = buf ^ 1;
            float* AsW = AsF + nb*A_BUF_F32;
            float* BsW = BsF + nb*B_BUF_F32;
            #pragma unroll
            for (int p = 0; p < 4; ++p) {
                int m = am + p*32;
                int unit = m*8 + (ak4 ^ (m & 7));
                *(float4*)(AsW + unit*4) = to_tf32x4(regA[p]);
            }
            #pragma unroll
            for (int p = 0; p < 4; ++p)
                *(float4*)(BsW + (bk + p*8)*B_STRIDE + bn4*4) = to_tf32x4(regB[p]);
        }
        __syncthreads();
        buf ^= 1;
    }

    // epilogue
    const int gr = lane >> 2, gc = (lane & 3) * 2;
    #pragma unroll
    for (int nt = 0; nt < 4; ++nt) {
        int col = bn + warpN*32 + nt*8 + gc;
        float b0v = bias ? bias[col]   : 0.0f;
        float b1v = bias ? bias[col+1] : 0.0f;
        #pragma unroll
        for (int mt = 0; mt < 4; ++mt) {
            int row = bm + warpM*64 + mt*16 + gr;
            float2 v0 = make_float2(acc[mt][nt][0] + b0v, acc[mt][nt][1] + b1v);
            float2 v1 = make_float2(acc[mt][nt][2] + b0v, acc[mt][nt][3] + b1v);
            *(float2*)(C + (size_t)row*N + col)     = v0;
            *(float2*)(C + (size_t)(row+8)*N + col) = v1;
        }
    }
}

// ---------------- fused sparse attention ----------------
// grid: (SEQ/AROWS, BSZ*NH), 256 threads (8 warps, 4 rows/warp)
__global__ __launch_bounds__(256) void attn_kernel(
    const float* __restrict__ qb, const float* __restrict__ kvb, float* __restrict__ ob)
{
    extern __shared__ float sm[];
    float* sc  = sm;                          // AROWS*SEQ
    float* skv = sc + AROWS*SEQ;              // ATC*KVSTRIDE
    float* sq  = skv + ATC*KVSTRIDE;          // AROWS*DHD
    int*   hist = (int*)(sq + AROWS*DHD);     // 8*256

    const int tid = threadIdx.x, lane = tid & 31, wid = tid >> 5;
    const int b = blockIdx.y >> 3, h = blockIdx.y & 7;
    const int row0 = blockIdx.x * AROWS;
    const int r0 = wid * 4;

    // ---- load Q tile (32x64) ----
    {
        int e = tid * 8;
        int r = e >> 6, dh = e & 63;
        const float* src = qb + ((size_t)(b*SEQ + row0 + r))*DMODEL + h*DHD + dh;
        float4 v0 = *(const float4*)src;
        float4 v1 = *(const float4*)(src + 4);
        *(float4*)(sq + r*DHD + dh)     = v0;
        *(float4*)(sq + r*DHD + dh + 4) = v1;
    }

    // ---- scores: sc[r][t] = q_r . k_t / 8 ----
    for (int c = 0; c < SEQ/ATC; ++c) {
        __syncthreads();
        #pragma unroll
        for (int j = 0; j < 8; ++j) {
            int idx4 = tid + j*256;
            int t = idx4 >> 4;
            int kk = (idx4 & 15) << 2;
            const float* src = kvb + ((size_t)(b*SEQ + c*ATC + t))*(2*DMODEL) + h*DHD + kk;
            float4 v = *(const float4*)src;
            *(float4*)(skv + t*KVSTRIDE + kk) = v;
        }
        __syncthreads();
        const float4* q04 = (const float4*)(sq + (r0+0)*DHD);
        const float4* q14 = (const float4*)(sq + (r0+1)*DHD);
        const float4* q24 = (const float4*)(sq + (r0+2)*DHD);
        const float4* q34 = (const float4*)(sq + (r0+3)*DHD);
        #pragma unroll
        for (int tl = 0; tl < 4; ++tl) {
            int t = tl*32 + lane;
            const float4* kp4 = (const float4*)(skv + t*KVSTRIDE);
            float a0=0.f, a1=0.f, a2=0.f, a3=0.f;
            #pragma unroll
            for (int kk = 0; kk < 16; ++kk) {
                float4 kv4 = kp4[kk];
                float4 qa = q04[kk], qb2 = q14[kk], qc = q24[kk], qd = q34[kk];
                a0 += kv4.x*qa.x  + kv4.y*qa.y  + kv4.z*qa.z  + kv4.w*qa.w;
                a1 += kv4.x*qb2.x + kv4.y*qb2.y + kv4.z*qb2.z + kv4.w*qb2.w;
                a2 += kv4.x*qc.x  + kv4.y*qc.y  + kv4.z*qc.z  + kv4.w*qc.w;
                a3 += kv4.x*qd.x  + kv4.y*qd.y  + kv4.z*qd.z  + kv4.w*qd.w;
            }
            int tg = c*ATC + t;
            sc[(r0+0)*SEQ+tg] = a0*0.125f;
            sc[(r0+1)*SEQ+tg] = a1*0.125f;
            sc[(r0+2)*SEQ+tg] = a2*0.125f;
            sc[(r0+3)*SEQ+tg] = a3*0.125f;
        }
    }

    // ---- per-row softmax + top-512 select + coefficient rewrite ----
    float invZ2[4];
    int* whist = hist + wid*256;
    for (int rr = 0; rr < 4; ++rr) {
        float* row = sc + (size_t)(r0+rr)*SEQ;

        float m = -3.4e38f;
        for (int t = lane; t < SEQ; t += 32) m = fmaxf(m, row[t]);
        m = warpMax(m);
        float z1 = 0.f;
        for (int t = lane; t < SEQ; t += 32) z1 += __expf(row[t] - m);
        z1 = warpSum(z1);
        float invZ1 = 1.0f / z1;

        // MSB radix select (4x8-bit): 512th largest score
        unsigned prefix = 0;
        int k = SEQ/2;
        #pragma unroll
        for (int shift = 24; shift >= 0; shift -= 8) {
            unsigned mask = (shift < 24) ? (0xffffffffu << (shift + 8)) : 0u;
            #pragma unroll
            for (int i = 0; i < 8; ++i) whist[lane*8 + i] = 0;
            __syncwarp();
            for (int t = lane; t < SEQ; t += 32) {
                unsigned key = f2key(row[t]);
                if (((key ^ prefix) & mask) == 0)
                    atomicAdd(&whist[(key >> shift) & 255], 1);
            }
            __syncwarp();
            // lane-parallel descending scan: lane L owns bins [L*8, L*8+8)
            int h8[8]; int v = 0;
            #pragma unroll
            for (int i = 0; i < 8; ++i) { h8[i] = whist[lane*8 + i]; v += h8[i]; }
            int inc = v;   // sum over lanes >= this lane
            #pragma unroll
            for (int o = 1; o < 32; o <<= 1) {
                int tt = __shfl_down_sync(0xffffffffu, inc, o);
                if (lane + o < 32) inc += tt;
            }
            int above = inc - v;
            int sel = -1, newk = 0;
            if (above < k && inc >= k) {
                int csum = above;
                #pragma unroll
                for (int j = 7; j >= 0; --j) {
                    int hc = h8[j];
                    if (csum + hc >= k) { sel = lane*8 + j; newk = k - csum; break; }
                    csum += hc;
                }
            }
            unsigned bal = __ballot_sync(0xffffffffu, sel >= 0);
            int src = __ffs(bal) - 1;
            sel = __shfl_sync(0xffffffffu, sel, src);
            k   = __shfl_sync(0xffffffffu, newk, src);
            prefix |= ((unsigned)sel) << shift;
        }
        const unsigned tauKey = prefix;
        const int needEq = k;   // #elements equal to tau kept (earliest indices, jax tie rule)

        if (lane == 0) whist[0] = 0;
        __syncwarp();
        float z2l = 0.f;
        for (int t = lane; t < SEQ; t += 32) {
            float s = row[t];
            unsigned key = f2key(s);
            float coef = 1.0f;
            if (key > tauKey) {
                coef = __expf(__expf(s - m) * invZ1);
            } else if (key == tauKey) {
                int p = atomicAdd(&whist[0], 1);
                if (p < 255) whist[1 + p] = t;
            }
            row[t] = coef;
            z2l += coef;
        }
        __syncwarp();
        float z2 = warpSum(z2l);
        int neq = whist[0];
        float stau = key2f(tauKey);
        float ctau = __expf(__expf(stau - m) * invZ1);
        int listN = neq < 255 ? neq : 255;
        for (int i = lane; i < listN; i += 32) {
            int t = whist[1 + i];
            int rank = 0;
            for (int j = 0; j < listN; ++j) rank += (whist[1 + j] < t);
            if (rank < needEq) row[t] = ctau;
        }
        int keptEq = needEq < neq ? needEq : neq;
        z2 += (ctau - 1.0f) * (float)keptEq;
        invZ2[rr] = 1.0f / z2;
        __syncwarp();
    }

    // ---- AV: o_r = (1/Z2) * sum_t coef_t * v_t ----
    float o00=0.f,o01=0.f,o10=0.f,o11=0.f,o20=0.f,o21=0.f,o30=0.f,o31=0.f;
    for (int c = 0; c < SEQ/ATC; ++c) {
        __syncthreads();
        #pragma unroll
        for (int j = 0; j < 8; ++j) {
            int idx4 = tid + j*256;
            int t = idx4 >> 4;
            int kk = (idx4 & 15) << 2;
            const float* src = kvb + ((size_t)(b*SEQ + c*ATC + t))*(2*DMODEL) + DMODEL + h*DHD + kk;
            float4 v = *(const float4*)src;
            *(float4*)(skv + t*KVSTRIDE + kk) = v;
        }
        __syncthreads();
        const float4* c0p = (const float4*)(sc + (size_t)(r0+0)*SEQ + c*ATC);
        const float4* c1p = (const float4*)(sc + (size_t)(r0+1)*SEQ + c*ATC);
        const float4* c2p = (const float4*)(sc + (size_t)(r0+2)*SEQ + c*ATC);
        const float4* c3p = (const float4*)(sc + (size_t)(r0+3)*SEQ + c*ATC);
        #pragma unroll 2
        for (int tq = 0; tq < ATC/4; ++tq) {
            float4 w0 = c0p[tq], w1 = c1p[tq], w2 = c2p[tq], w3 = c3p[tq];
            const float* w0a = (const float*)&w0;
            const float* w1a = (const float*)&w1;
            const float* w2a = (const float*)&w2;
            const float* w3a = (const float*)&w3;
            #pragma unroll
            for (int j = 0; j < 4; ++j) {
                int t = tq*4 + j;
                float v0 = skv[t*KVSTRIDE + lane];
                float v1 = skv[t*KVSTRIDE + lane + 32];
                o00 += w0a[j]*v0; o01 += w0a[j]*v1;
                o10 += w1a[j]*v0; o11 += w1a[j]*v1;
                o20 += w2a[j]*v0; o21 += w2a[j]*v1;
                o30 += w3a[j]*v0; o31 += w3a[j]*v1;
            }
        }
    }
    {
        size_t base = ((size_t)(b*SEQ + row0 + r0))*DMODEL + h*DHD;
        ob[base + 0*DMODEL + lane]      = o00*invZ2[0];
        ob[base + 0*DMODEL + lane + 32] = o01*invZ2[0];
        ob[base + 1*DMODEL + lane]      = o10*invZ2[1];
        ob[base + 1*DMODEL + lane + 32] = o11*invZ2[1];
        ob[base + 2*DMODEL + lane]      = o20*invZ2[2];
        ob[base + 2*DMODEL + lane + 32] = o21*invZ2[2];
        ob[base + 3*DMODEL + lane]      = o30*invZ2[3];
        ob[base + 3*DMODEL + lane + 32] = o31*invZ2[3];
    }
}

// ---------------- residual + RMSNorm (per row of 512) ----------------
__global__ __launch_bounds__(128) void rms_add_kernel(
    const float* __restrict__ x, const float* __restrict__ a,
    const float* __restrict__ w, float* __restrict__ out)
{
    __shared__ float red[4];
    int row = blockIdx.x;
    int t = threadIdx.x;
    const float4* x4 = (const float4*)(x + (size_t)row*DMODEL);
    const float4* a4 = (const float4*)(a + (size_t)row*DMODEL);
    float4 xv = x4[t], av = a4[t];
    float4 s = make_float4(xv.x+av.x, xv.y+av.y, xv.z+av.z, xv.w+av.w);
    float ss = s.x*s.x + s.y*s.y + s.z*s.z + s.w*s.w;
    ss = warpSum(ss);
    if ((t & 31) == 0) red[t >> 5] = ss;
    __syncthreads();
    float tot = red[0] + red[1] + red[2] + red[3];
    float inv = rsqrtf(tot * (1.0f/DMODEL) + 1e-6f);
    float4 wv = ((const float4*)w)[t];
    float4 o = make_float4(s.x*inv*wv.x, s.y*inv*wv.y, s.z*inv*wv.z, s.w*inv*wv.w);
    ((float4*)(out + (size_t)row*DMODEL))[t] = o;
}

// ---------------- silu(u1)*u2 ----------------
__global__ void silu_mul_kernel(const float* __restrict__ u1, const float* __restrict__ u2,
                                float* __restrict__ g, int n4)
{
    int i = blockIdx.x*blockDim.x + threadIdx.x;
    if (i < n4) {
        float4 a = ((const float4*)u1)[i];
        float4 bb = ((const float4*)u2)[i];
        float4 r;
        r.x = a.x / (1.f + __expf(-a.x)) * bb.x;
        r.y = a.y / (1.f + __expf(-a.y)) * bb.y;
        r.z = a.z / (1.f + __expf(-a.z)) * bb.z;
        r.w = a.w / (1.f + __expf(-a.w)) * bb.w;
        ((float4*)g)[i] = r;
    }
}

// ---------------- instance norm over sequence dim ----------------
__global__ __launch_bounds__(256) void in1_kernel(
    const float* __restrict__ hh, const float* __restrict__ ffn,
    float* __restrict__ y, float* __restrict__ psum, float* __restrict__ psq)
{
    int b = blockIdx.y, chunk = blockIdx.x;
    int s0 = chunk * 32;
    int t = threadIdx.x;
    float s_[2] = {0.f, 0.f}, q_[2] = {0.f, 0.f};
    for (int s = 0; s < 32; ++s) {
        size_t base = ((size_t)(b*SEQ + s0 + s))*DMODEL;
        #pragma unroll
        for (int u = 0; u < 2; ++u) {
            int d = t + u*256;
            float yv = hh[base + d] + ffn[base + d];
            y[base + d] = yv;
            s_[u] += yv; q_[u] += yv*yv;
        }
    }
    #pragma unroll
    for (int u = 0; u < 2; ++u) {
        size_t pidx = ((size_t)b*32 + chunk)*DMODEL + t + u*256;
        psum[pidx] = s_[u];
        psq [pidx] = q_[u];
    }
}

__global__ void in2_kernel(const float* __restrict__ psum, const float* __restrict__ psq,
                           float* __restrict__ mean, float* __restrict__ rstd)
{
    int b = blockIdx.x, d = threadIdx.x;
    float s = 0.f, q = 0.f;
    for (int c = 0; c < 32; ++c) {
        size_t pidx = ((size_t)b*32 + c)*DMODEL + d;
        s += psum[pidx]; q += psq[pidx];
    }
    float m = s * (1.0f/SEQ);
    float v = q * (1.0f/SEQ) - m*m;
    mean[b*DMODEL + d] = m;
    rstd[b*DMODEL + d] = rsqrtf(v + 1e-5f);
}

__global__ void in3_kernel(const float* __restrict__ y, const float* __restrict__ mean,
                           const float* __restrict__ rstd, const float* __restrict__ w,
                           const float* __restrict__ bb, float* __restrict__ out)
{
    int i = blockIdx.x*blockDim.x + threadIdx.x;
    if (i < MTOT*DMODEL) {
        int d = i & (DMODEL - 1);
        int b = i >> 19;  // SEQ*DMODEL = 2^19
        float m = mean[b*DMODEL + d], r = rstd[b*DMODEL + d];
        out[i] = (y[i] - m) * r * w[d] + bb[d];
    }
}

// ---------------- launch ----------------
extern "C" void kernel_launch(void* const* d_in, const int* in_sizes, int n_in,
                              void* d_out, int out_size)
{
    (void)in_sizes; (void)n_in; (void)out_size;
    const float* x    = (const float*)d_in[0];
    const float* Wq   = (const float*)d_in[1];
    const float* bq   = (const float*)d_in[2];
    const float* Wkv  = (const float*)d_in[3];
    const float* bkv  = (const float*)d_in[4];
    const float* Wo   = (const float*)d_in[5];
    const float* bo   = (const float*)d_in[6];
    const float* rmsw = (const float*)d_in[7];
    const float* l1   = (const float*)d_in[8];
    const float* l2   = (const float*)d_in[9];
    const float* l3   = (const float*)d_in[10];
    const float* inw  = (const float*)d_in[11];
    const float* inb  = (const float*)d_in[12];
    float* out = (float*)d_out;

    float *q, *kv, *o, *att, *hbuf, *u1, *u2, *gate, *ffn, *y, *ps, *pq, *mn, *rs;
    cudaGetSymbolAddress((void**)&q,    g_q);
    cudaGetSymbolAddress((void**)&kv,   g_kv);
    cudaGetSymbolAddress((void**)&o,    g_o);
    cudaGetSymbolAddress((void**)&att,  g_att);
    cudaGetSymbolAddress((void**)&hbuf, g_h);
    cudaGetSymbolAddress((void**)&u1,   g_u1);
    cudaGetSymbolAddress((void**)&u2,   g_u2);
    cudaGetSymbolAddress((void**)&gate, g_gate);
    cudaGetSymbolAddress((void**)&ffn,  g_ffn);
    cudaGetSymbolAddress((void**)&y,    g_y);
    cudaGetSymbolAddress((void**)&ps,   g_psum);
    cudaGetSymbolAddress((void**)&pq,   g_psq);
    cudaGetSymbolAddress((void**)&mn,   g_mean);
    cudaGetSymbolAddress((void**)&rs,   g_rstd);

    const int attnSmem = (AROWS*SEQ + ATC*KVSTRIDE + AROWS*DHD + 8*256) * 4;
    cudaFuncSetAttribute(attn_kernel, cudaFuncAttributeMaxDynamicSharedMemorySize, attnSmem);
    const int gemmSmem = (2*A_BUF_F32 + 2*B_BUF_F32) * 4;   // 67584 B
    cudaFuncSetAttribute(tf32gemm_kernel, cudaFuncAttributeMaxDynamicSharedMemorySize, gemmSmem);

    // QKV projections
    tf32gemm_kernel<<<dim3(DMODEL/128,   MTOT/128), 256, gemmSmem>>>(x, Wq,  bq,  q,  MTOT, DMODEL,   DMODEL);
    tf32gemm_kernel<<<dim3(2*DMODEL/128, MTOT/128), 256, gemmSmem>>>(x, Wkv, bkv, kv, MTOT, 2*DMODEL, DMODEL);

    // sparse attention
    attn_kernel<<<dim3(SEQ/AROWS, BSZ*NH), 256, attnSmem>>>(q, kv, o);

    // output projection + residual + rmsnorm
    tf32gemm_kernel<<<dim3(DMODEL/128, MTOT/128), 256, gemmSmem>>>(o, Wo, bo, att, MTOT, DMODEL, DMODEL);
    rms_add_kernel<<<MTOT, 128>>>(x, att, rmsw, hbuf);

    // SwiGLU FFN
    tf32gemm_kernel<<<dim3(INNER_DIM/128, MTOT/128), 256, gemmSmem>>>(hbuf, l1, nullptr, u1, MTOT, INNER_DIM, DMODEL);
    tf32gemm_kernel<<<dim3(INNER_DIM/128, MTOT/128), 256, gemmSmem>>>(hbuf, l2, nullptr, u2, MTOT, INNER_DIM, DMODEL);
    silu_mul_kernel<<<(MTOT*INNER_DIM/4 + 255)/256, 256>>>(u1, u2, gate, MTOT*INNER_DIM/4);
    tf32gemm_kernel<<<dim3(DMODEL/128, MTOT/128), 256, gemmSmem>>>(gate, l3, nullptr, ffn, MTOT, DMODEL, INNER_DIM);

    // instance norm over sequence
    in1_kernel<<<dim3(32, BSZ), 256>>>(hbuf, ffn, y, ps, pq);
    in2_kernel<<<BSZ, DMODEL>>>(ps, pq, mn, rs);
    in3_kernel<<<(MTOT*DMODEL + 255)/256, 256>>>(y, mn, rs, inw, inb, out);
}

// round 6
// speedup vs baseline: 3.2160x; 1.0081x over previous
#include <cuda_runtime.h>
#include <math.h>

#define BSZ 4
#define SEQ 1024
#define DMODEL 512
#define NH 8
#define DHD 64
#define INNER_DIM 1536
#define MTOT (BSZ*SEQ)   /* 4096 */

#define AROWS 32
#define ATC 128
#define KVSTRIDE 68      /* 17 x 16B (odd) -> conflict-free phases */
#define SCSTRIDE 1032

// ---------------- scratch (device globals; no runtime allocation) ----------------
__device__ float g_q   [MTOT*DMODEL];
__device__ float g_kv  [MTOT*2*DMODEL];
__device__ float g_o   [MTOT*DMODEL];
__device__ float g_att [MTOT*DMODEL];
__device__ float g_h   [MTOT*DMODEL];
__device__ float g_u1  [MTOT*INNER_DIM];
__device__ float g_u2  [MTOT*INNER_DIM];
__device__ float g_gate[MTOT*INNER_DIM];
__device__ float g_ffn [MTOT*DMODEL];
__device__ float g_y   [MTOT*DMODEL];
__device__ float g_psum[BSZ*32*DMODEL];
__device__ float g_psq [BSZ*32*DMODEL];
__device__ float g_mean[BSZ*DMODEL];
__device__ float g_rstd[BSZ*DMODEL];

// ---------------- helpers ----------------
__device__ __forceinline__ unsigned f2key(float f) {
    unsigned u = __float_as_uint(f);
    return (u & 0x80000000u) ? ~u : (u | 0x80000000u);
}
__device__ __forceinline__ float key2f(unsigned k) {
    unsigned u = (k & 0x80000000u) ? (k & 0x7fffffffu) : ~k;
    return __uint_as_float(u);
}
__device__ __forceinline__ float warpMax(float v) {
    #pragma unroll
    for (int o = 16; o; o >>= 1) v = fmaxf(v, __shfl_xor_sync(0xffffffffu, v, o));
    return v;
}
__device__ __forceinline__ float warpSum(float v) {
    #pragma unroll
    for (int o = 16; o; o >>= 1) v += __shfl_xor_sync(0xffffffffu, v, o);
    return v;
}
__device__ __forceinline__ unsigned to_tf32(float x) {
    unsigned u;
    asm("cvt.rna.tf32.f32 %0, %1;" : "=r"(u) : "f"(x));
    return u;
}
__device__ __forceinline__ float4 to_tf32x4(float4 v) {
    float4 r;
    r.x = __uint_as_float(to_tf32(v.x));
    r.y = __uint_as_float(to_tf32(v.y));
    r.z = __uint_as_float(to_tf32(v.z));
    r.w = __uint_as_float(to_tf32(v.w));
    return r;
}
__device__ __forceinline__ void ldsm4(unsigned* r, unsigned saddr) {
    asm volatile("ldmatrix.sync.aligned.m8n8.x4.shared.b16 {%0,%1,%2,%3}, [%4];"
                 : "=r"(r[0]), "=r"(r[1]), "=r"(r[2]), "=r"(r[3]) : "r"(saddr));
}
__device__ __forceinline__ void mma_tf32(float* d, const unsigned* a, const unsigned* b) {
    asm volatile(
        "mma.sync.aligned.m16n8k8.row.col.f32.tf32.tf32.f32 "
        "{%0,%1,%2,%3}, {%4,%5,%6,%7}, {%8,%9}, {%0,%1,%2,%3};"
        : "+f"(d[0]), "+f"(d[1]), "+f"(d[2]), "+f"(d[3])
        : "r"(a[0]), "r"(a[1]), "r"(a[2]), "r"(a[3]), "r"(b[0]), "r"(b[1]));
}

// ---------------- TF32 tensor-core GEMM: C[M,N] = A[M,K] @ B[K,N] (+bias) ----------------
#define GBK 32
#define A_BUF_F32 4096           /* 128*32 */
#define B_STRIDE 136             /* 128 + 8 pad */
#define B_BUF_F32 (GBK*B_STRIDE) /* 4352 */

__global__ __launch_bounds__(256, 2) void tf32gemm_kernel(
    const float* __restrict__ A, const float* __restrict__ B,
    const float* __restrict__ bias, float* __restrict__ C,
    int M, int N, int K)
{
    extern __shared__ float gsm[];
    float* AsF = gsm;                    // 2 * 4096
    float* BsF = gsm + 2*A_BUF_F32;      // 2 * 4352
    const unsigned asBase = (unsigned)__cvta_generic_to_shared(AsF);

    const int tid = threadIdx.x, lane = tid & 31, wid = tid >> 5;
    const int warpM = wid & 1, warpN = wid >> 1;
    const int bm = blockIdx.y * 128, bn = blockIdx.x * 128;

    const int mbase = warpM*64 + ((lane>>3)&1)*8 + (lane&7);
    const int jhi   = lane >> 4;
    const int xorv  = lane & 7;
    const int kb    = lane & 3;
    const int nbase = warpN*32 + (lane>>2);

    float acc[4][4][4];
    #pragma unroll
    for (int mt = 0; mt < 4; ++mt)
        #pragma unroll
        for (int nt = 0; nt < 4; ++nt)
            #pragma unroll
            for (int i = 0; i < 4; ++i) acc[mt][nt][i] = 0.0f;

    const int am = tid >> 3, ak4 = tid & 7;
    const int bk = tid >> 5, bn4 = tid & 31;

    float4 regA[4], regB[4];
    #pragma unroll
    for (int p = 0; p < 4; ++p)
        regA[p] = *(const float4*)(A + (size_t)(bm + am + p*32)*K + ak4*4);
    #pragma unroll
    for (int p = 0; p < 4; ++p)
        regB[p] = *(const float4*)(B + (size_t)(bk + p*8)*N + bn + bn4*4);
    #pragma unroll
    for (int p = 0; p < 4; ++p) {
        int m = am + p*32;
        int unit = m*8 + (ak4 ^ (m & 7));
        *(float4*)(AsF + unit*4) = to_tf32x4(regA[p]);
    }
    #pragma unroll
    for (int p = 0; p < 4; ++p)
        *(float4*)(BsF + (bk + p*8)*B_STRIDE + bn4*4) = to_tf32x4(regB[p]);
    __syncthreads();

    const int nIter = K / GBK;
    int buf = 0;
    for (int kt = 0; kt < nIter; ++kt) {
        bool more = (kt + 1 < nIter);
        if (more) {
            int k0 = (kt+1)*GBK;
            #pragma unroll
            for (int p = 0; p < 4; ++p)
                regA[p] = *(const float4*)(A + (size_t)(bm + am + p*32)*K + k0 + ak4*4);
            #pragma unroll
            for (int p = 0; p < 4; ++p)
                regB[p] = *(const float4*)(B + (size_t)(k0 + bk + p*8)*N + bn + bn4*4);
        }

        const unsigned aBufBase = asBase + buf*(A_BUF_F32*4);
        const float* bb = BsF + buf*B_BUF_F32;
        #pragma unroll
        for (int ks = 0; ks < 4; ++ks) {
            unsigned af[4][4];
            #pragma unroll
            for (int mt = 0; mt < 4; ++mt) {
                int m = mbase + mt*16;
                int unit = m*8 + ((ks*2 + jhi) ^ xorv);
                ldsm4(af[mt], aBufBase + unit*16);
            }
            unsigned bf[4][2];
            #pragma unroll
            for (int nt = 0; nt < 4; ++nt) {
                bf[nt][0] = __float_as_uint(bb[(ks*8 + kb    )*B_STRIDE + nbase + nt*8]);
                bf[nt][1] = __float_as_uint(bb[(ks*8 + kb + 4)*B_STRIDE + nbase + nt*8]);
            }
            #pragma unroll
            for (int mt = 0; mt < 4; ++mt)
                #pragma unroll
                for (int nt = 0; nt < 4; ++nt)
                    mma_tf32(acc[mt][nt], af[mt], bf[nt]);
        }

        if (more) {
            int nb = buf ^ 1;
            float* AsW = AsF + nb*A_BUF_F32;
            float* BsW = BsF + nb*B_BUF_F32;
            #pragma unroll
            for (int p = 0; p < 4; ++p) {
                int m = am + p*32;
                int unit = m*8 + (ak4 ^ (m & 7));
                *(float4*)(AsW + unit*4) = to_tf32x4(regA[p]);
            }
            #pragma unroll
            for (int p = 0; p < 4; ++p)
                *(float4*)(BsW + (bk + p*8)*B_STRIDE + bn4*4) = to_tf32x4(regB[p]);
        }
        __syncthreads();
        buf ^= 1;
    }

    const int gr = lane >> 2, gc = (lane & 3) * 2;
    #pragma unroll
    for (int nt = 0; nt < 4; ++nt) {
        int col = bn + warpN*32 + nt*8 + gc;
        float b0v = bias ? bias[col]   : 0.0f;
        float b1v = bias ? bias[col+1] : 0.0f;
        #pragma unroll
        for (int mt = 0; mt < 4; ++mt) {
            int row = bm + warpM*64 + mt*16 + gr;
            float2 v0 = make_float2(acc[mt][nt][0] + b0v, acc[mt][nt][1] + b1v);
            float2 v1 = make_float2(acc[mt][nt][2] + b0v, acc[mt][nt][3] + b1v);
            *(float2*)(C + (size_t)row*N + col)     = v0;
            *(float2*)(C + (size_t)(row+8)*N + col) = v1;
        }
    }
}

// ---------------- fused sparse attention (mma scores + AV, match-based select) ----------------
// grid: (SEQ/AROWS, BSZ*NH), 256 threads (8 warps)
__global__ __launch_bounds__(256) void attn_kernel(
    const float* __restrict__ qb, const float* __restrict__ kvb, float* __restrict__ ob)
{
    extern __shared__ float sm[];
    float* sc   = sm;                              // AROWS * SCSTRIDE
    float* skv  = sc + AROWS*SCSTRIDE;             // ATC * KVSTRIDE
    float* sq   = skv + ATC*KVSTRIDE;              // AROWS * KVSTRIDE
    float* sinv = sq + AROWS*KVSTRIDE;             // AROWS
    int*   hist = (int*)(sinv + AROWS);            // 8*256

    const int tid = threadIdx.x, lane = tid & 31, wid = tid >> 5;
    const int b = blockIdx.y >> 3, h = blockIdx.y & 7;
    const int row0 = blockIdx.x * AROWS;
    const int g = lane >> 2, fb = lane & 3;   // fragment geometry

    // ---- load Q tile (32x64, tf32-rounded) ----
    {
        int r = tid >> 3, dh = (tid & 7) << 3;
        const float* src = qb + ((size_t)(b*SEQ + row0 + r))*DMODEL + h*DHD + dh;
        *(float4*)(sq + r*KVSTRIDE + dh)     = to_tf32x4(*(const float4*)src);
        *(float4*)(sq + r*KVSTRIDE + dh + 4) = to_tf32x4(*(const float4*)(src + 4));
    }

    // ---- scores via mma: sc[r][t] = (q_r . k_t)/8 ----
    const int t0w = wid * 16;     // warp's t-slice within chunk
    for (int c = 0; c < SEQ/ATC; ++c) {
        __syncthreads();
        #pragma unroll
        for (int j = 0; j < 8; ++j) {
            int idx4 = tid + j*256;
            int t = idx4 >> 4;
            int kk = (idx4 & 15) << 2;
            const float* src = kvb + ((size_t)(b*SEQ + c*ATC + t))*(2*DMODEL) + h*DHD + kk;
            *(float4*)(skv + t*KVSTRIDE + kk) = to_tf32x4(*(const float4*)src);
        }
        __syncthreads();

        float acc[2][2][4];
        #pragma unroll
        for (int mt = 0; mt < 2; ++mt)
            #pragma unroll
            for (int nt = 0; nt < 2; ++nt)
                #pragma unroll
                for (int i = 0; i < 4; ++i) acc[mt][nt][i] = 0.0f;

        #pragma unroll
        for (int ks = 0; ks < 8; ++ks) {
            unsigned af[2][4], bf[2][2];
            #pragma unroll
            for (int mt = 0; mt < 2; ++mt) {
                const float* ap = sq + (mt*16 + g)*KVSTRIDE + ks*8 + fb;
                af[mt][0] = __float_as_uint(ap[0]);
                af[mt][1] = __float_as_uint(ap[8*KVSTRIDE]);
                af[mt][2] = __float_as_uint(ap[4]);
                af[mt][3] = __float_as_uint(ap[8*KVSTRIDE + 4]);
            }
            #pragma unroll
            for (int nt = 0; nt < 2; ++nt) {
                const float* bp = skv + (t0w + nt*8 + g)*KVSTRIDE + ks*8 + fb;
                bf[nt][0] = __float_as_uint(bp[0]);
                bf[nt][1] = __float_as_uint(bp[4]);
            }
            #pragma unroll
            for (int mt = 0; mt < 2; ++mt)
                #pragma unroll
                for (int nt = 0; nt < 2; ++nt)
                    mma_tf32(acc[mt][nt], af[mt], bf[nt]);
        }
        #pragma unroll
        for (int mt = 0; mt < 2; ++mt)
            #pragma unroll
            for (int nt = 0; nt < 2; ++nt) {
                int col = c*ATC + t0w + nt*8 + 2*fb;
                int rlo = mt*16 + g;
                *(float2*)(sc + (size_t)rlo*SCSTRIDE + col) =
                    make_float2(acc[mt][nt][0]*0.125f, acc[mt][nt][1]*0.125f);
                *(float2*)(sc + (size_t)(rlo+8)*SCSTRIDE + col) =
                    make_float2(acc[mt][nt][2]*0.125f, acc[mt][nt][3]*0.125f);
            }
    }
    __syncthreads();   // all scores written

    // ---- per-row softmax + top-512 select + coefficient rewrite ----
    const int r0 = wid * 4;
    int* whist = hist + wid*256;
    for (int rr = 0; rr < 4; ++rr) {
        float* row = sc + (size_t)(r0+rr)*SCSTRIDE;

        float m = -3.4e38f;
        for (int t = lane; t < SEQ; t += 32) m = fmaxf(m, row[t]);
        m = warpMax(m);
        float z1 = 0.f;
        for (int t = lane; t < SEQ; t += 32) z1 += __expf(row[t] - m);
        z1 = warpSum(z1);
        float invZ1 = 1.0f / z1;

        // MSB radix select (4x8-bit), match_any histogram (no atomics)
        unsigned prefix = 0;
        int k = SEQ/2;
        #pragma unroll
        for (int shift = 24; shift >= 0; shift -= 8) {
            unsigned mask = (shift < 24) ? (0xffffffffu << (shift + 8)) : 0u;
            #pragma unroll
            for (int i = 0; i < 8; ++i) whist[lane*8 + i] = 0;
            __syncwarp();
            for (int t = lane; t < SEQ; t += 32) {
                unsigned key = f2key(row[t]);
                bool ok = ((key ^ prefix) & mask) == 0u;
                unsigned digit = ok ? ((key >> shift) & 255u) : 0xffffffffu;
                unsigned grp = __match_any_sync(0xffffffffu, digit);
                bool leader = ((int)__ffs(grp) - 1) == lane;
                if (ok && leader) whist[digit] += __popc(grp);
            }
            __syncwarp();
            int h8[8]; int v = 0;
            #pragma unroll
            for (int i = 0; i < 8; ++i) { h8[i] = whist[lane*8 + i]; v += h8[i]; }
            int inc = v;
            #pragma unroll
            for (int o = 1; o < 32; o <<= 1) {
                int tt = __shfl_down_sync(0xffffffffu, inc, o);
                if (lane + o < 32) inc += tt;
            }
            int above = inc - v;
            int sel = -1, newk = 0;
            if (above < k && inc >= k) {
                int csum = above;
                #pragma unroll
                for (int j = 7; j >= 0; --j) {
                    int hc = h8[j];
                    if (csum + hc >= k) { sel = lane*8 + j; newk = k - csum; break; }
                    csum += hc;
                }
            }
            unsigned bal = __ballot_sync(0xffffffffu, sel >= 0);
            int src = __ffs(bal) - 1;
            sel = __shfl_sync(0xffffffffu, sel, src);
            k   = __shfl_sync(0xffffffffu, newk, src);
            prefix |= ((unsigned)sel) << shift;
        }
        const unsigned tauKey = prefix;
        const int needEq = k;

        if (lane == 0) whist[0] = 0;
        __syncwarp();
        float z2l = 0.f;
        for (int t = lane; t < SEQ; t += 32) {
            float s = row[t];
            unsigned key = f2key(s);
            float coef = 1.0f;
            if (key > tauKey) {
                coef = __uint_as_float(to_tf32(__expf(__expf(s - m) * invZ1)));
            } else if (key == tauKey) {
                int p = atomicAdd(&whist[0], 1);
                if (p < 255) whist[1 + p] = t;
            }
            row[t] = coef;
            z2l += coef;
        }
        __syncwarp();
        float z2 = warpSum(z2l);
        int neq = whist[0];
        float stau = key2f(tauKey);
        float ctau = __uint_as_float(to_tf32(__expf(__expf(stau - m) * invZ1)));
        int listN = neq < 255 ? neq : 255;
        for (int i = lane; i < listN; i += 32) {
            int t = whist[1 + i];
            int rank = 0;
            for (int j = 0; j < listN; ++j) rank += (whist[1 + j] < t);
            if (rank < needEq) row[t] = ctau;
        }
        int keptEq = needEq < neq ? needEq : neq;
        z2 += (ctau - 1.0f) * (float)keptEq;
        if (lane == 0) sinv[r0 + rr] = 1.0f / z2;
        __syncwarp();
    }
    __syncthreads();   // coefs + sinv ready

    // ---- AV via mma: O[32x64] = W[32x1024] @ V[1024x64] ----
    const int m0 = (wid >> 2) * 16;
    const int nsel = (wid & 3) * 8;
    float oacc[2][4];
    #pragma unroll
    for (int nt = 0; nt < 2; ++nt)
        #pragma unroll
        for (int i = 0; i < 4; ++i) oacc[nt][i] = 0.0f;

    for (int c = 0; c < SEQ/ATC; ++c) {
        __syncthreads();
        #pragma unroll
        for (int j = 0; j < 8; ++j) {
            int idx4 = tid + j*256;
            int t = idx4 >> 4;
            int kk = (idx4 & 15) << 2;
            const float* src = kvb + ((size_t)(b*SEQ + c*ATC + t))*(2*DMODEL) + DMODEL + h*DHD + kk;
            *(float4*)(skv + t*KVSTRIDE + kk) = to_tf32x4(*(const float4*)src);
        }
        __syncthreads();

        #pragma unroll
        for (int ks = 0; ks < 16; ++ks) {
            unsigned af[4], bf[2][2];
            const float* ap = sc + (size_t)(m0 + g)*SCSTRIDE + c*ATC + ks*8 + fb;
            af[0] = __float_as_uint(ap[0]);
            af[1] = __float_as_uint(ap[8*SCSTRIDE]);
            af[2] = __float_as_uint(ap[4]);
            af[3] = __float_as_uint(ap[8*SCSTRIDE + 4]);
            const float* bp = skv + (ks*8 + fb)*KVSTRIDE + nsel + g;
            bf[0][0] = __float_as_uint(bp[0]);
            bf[0][1] = __float_as_uint(bp[4*KVSTRIDE]);
            bf[1][0] = __float_as_uint(bp[32]);
            bf[1][1] = __float_as_uint(bp[4*KVSTRIDE + 32]);
            mma_tf32(oacc[0], af, bf[0]);
            mma_tf32(oacc[1], af, bf[1]);
        }
    }

    // epilogue: scale by 1/Z2, store
    {
        float izLo = sinv[m0 + g];
        float izHi = sinv[m0 + g + 8];
        size_t rLo = (size_t)(b*SEQ + row0 + m0 + g)*DMODEL;
        size_t rHi = rLo + 8*DMODEL;
        #pragma unroll
        for (int nt = 0; nt < 2; ++nt) {
            int col = h*DHD + nsel + nt*32 + 2*fb;
            *(float2*)(ob + rLo + col) = make_float2(oacc[nt][0]*izLo, oacc[nt][1]*izLo);
            *(float2*)(ob + rHi + col) = make_float2(oacc[nt][2]*izHi, oacc[nt][3]*izHi);
        }
    }
}

// ---------------- residual + RMSNorm (per row of 512) ----------------
__global__ __launch_bounds__(128) void rms_add_kernel(
    const float* __restrict__ x, const float* __restrict__ a,
    const float* __restrict__ w, float* __restrict__ out)
{
    __shared__ float red[4];
    int row = blockIdx.x;
    int t = threadIdx.x;
    const float4* x4 = (const float4*)(x + (size_t)row*DMODEL);
    const float4* a4 = (const float4*)(a + (size_t)row*DMODEL);
    float4 xv = x4[t], av = a4[t];
    float4 s = make_float4(xv.x+av.x, xv.y+av.y, xv.z+av.z, xv.w+av.w);
    float ss = s.x*s.x + s.y*s.y + s.z*s.z + s.w*s.w;
    ss = warpSum(ss);
    if ((t & 31) == 0) red[t >> 5] = ss;
    __syncthreads();
    float tot = red[0] + red[1] + red[2] + red[3];
    float inv = rsqrtf(tot * (1.0f/DMODEL) + 1e-6f);
    float4 wv = ((const float4*)w)[t];
    float4 o = make_float4(s.x*inv*wv.x, s.y*inv*wv.y, s.z*inv*wv.z, s.w*inv*wv.w);
    ((float4*)(out + (size_t)row*DMODEL))[t] = o;
}

// ---------------- silu(u1)*u2 ----------------
__global__ void silu_mul_kernel(const float* __restrict__ u1, const float* __restrict__ u2,
                                float* __restrict__ g, int n4)
{
    int i = blockIdx.x*blockDim.x + threadIdx.x;
    if (i < n4) {
        float4 a = ((const float4*)u1)[i];
        float4 bb = ((const float4*)u2)[i];
        float4 r;
        r.x = a.x / (1.f + __expf(-a.x)) * bb.x;
        r.y = a.y / (1.f + __expf(-a.y)) * bb.y;
        r.z = a.z / (1.f + __expf(-a.z)) * bb.z;
        r.w = a.w / (1.f + __expf(-a.w)) * bb.w;
        ((float4*)g)[i] = r;
    }
}

// ---------------- instance norm over sequence dim ----------------
__global__ __launch_bounds__(256) void in1_kernel(
    const float* __restrict__ hh, const float* __restrict__ ffn,
    float* __restrict__ y, float* __restrict__ psum, float* __restrict__ psq)
{
    int b = blockIdx.y, chunk = blockIdx.x;
    int s0 = chunk * 32;
    int t = threadIdx.x;
    float s_[2] = {0.f, 0.f}, q_[2] = {0.f, 0.f};
    for (int s = 0; s < 32; ++s) {
        size_t base = ((size_t)(b*SEQ + s0 + s))*DMODEL;
        #pragma unroll
        for (int u = 0; u < 2; ++u) {
            int d = t + u*256;
            float yv = hh[base + d] + ffn[base + d];
            y[base + d] = yv;
            s_[u] += yv; q_[u] += yv*yv;
        }
    }
    #pragma unroll
    for (int u = 0; u < 2; ++u) {
        size_t pidx = ((size_t)b*32 + chunk)*DMODEL + t + u*256;
        psum[pidx] = s_[u];
        psq [pidx] = q_[u];
    }
}

__global__ void in2_kernel(const float* __restrict__ psum, const float* __restrict__ psq,
                           float* __restrict__ mean, float* __restrict__ rstd)
{
    int b = blockIdx.x, d = threadIdx.x;
    float s = 0.f, q = 0.f;
    for (int c = 0; c < 32; ++c) {
        size_t pidx = ((size_t)b*32 + c)*DMODEL + d;
        s += psum[pidx]; q += psq[pidx];
    }
    float m = s * (1.0f/SEQ);
    float v = q * (1.0f/SEQ) - m*m;
    mean[b*DMODEL + d] = m;
    rstd[b*DMODEL + d] = rsqrtf(v + 1e-5f);
}

__global__ void in3_kernel(const float* __restrict__ y, const float* __restrict__ mean,
                           const float* __restrict__ rstd, const float* __restrict__ w,
                           const float* __restrict__ bb, float* __restrict__ out)
{
    int i = blockIdx.x*blockDim.x + threadIdx.x;
    if (i < MTOT*DMODEL) {
        int d = i & (DMODEL - 1);
        int b = i >> 19;  // SEQ*DMODEL = 2^19
        float m = mean[b*DMODEL + d], r = rstd[b*DMODEL + d];
        out[i] = (y[i] - m) * r * w[d] + bb[d];
    }
}

// ---------------- launch ----------------
extern "C" void kernel_launch(void* const* d_in, const int* in_sizes, int n_in,
                              void* d_out, int out_size)
{
    (void)in_sizes; (void)n_in; (void)out_size;
    const float* x    = (const float*)d_in[0];
    const float* Wq   = (const float*)d_in[1];
    const float* bq   = (const float*)d_in[2];
    const float* Wkv  = (const float*)d_in[3];
    const float* bkv  = (const float*)d_in[4];
    const float* Wo   = (const float*)d_in[5];
    const float* bo   = (const float*)d_in[6];
    const float* rmsw = (const float*)d_in[7];
    const float* l1   = (const float*)d_in[8];
    const float* l2   = (const float*)d_in[9];
    const float* l3   = (const float*)d_in[10];
    const float* inw  = (const float*)d_in[11];
    const float* inb  = (const float*)d_in[12];
    float* out = (float*)d_out;

    float *q, *kv, *o, *att, *hbuf, *u1, *u2, *gate, *ffn, *y, *ps, *pq, *mn, *rs;
    cudaGetSymbolAddress((void**)&q,    g_q);
    cudaGetSymbolAddress((void**)&kv,   g_kv);
    cudaGetSymbolAddress((void**)&o,    g_o);
    cudaGetSymbolAddress((void**)&att,  g_att);
    cudaGetSymbolAddress((void**)&hbuf, g_h);
    cudaGetSymbolAddress((void**)&u1,   g_u1);
    cudaGetSymbolAddress((void**)&u2,   g_u2);
    cudaGetSymbolAddress((void**)&gate, g_gate);
    cudaGetSymbolAddress((void**)&ffn,  g_ffn);
    cudaGetSymbolAddress((void**)&y,    g_y);
    cudaGetSymbolAddress((void**)&ps,   g_psum);
    cudaGetSymbolAddress((void**)&pq,   g_psq);
    cudaGetSymbolAddress((void**)&mn,   g_mean);
    cudaGetSymbolAddress((void**)&rs,   g_rstd);

    const int attnSmem = (AROWS*SCSTRIDE + ATC*KVSTRIDE + AROWS*KVSTRIDE + AROWS) * 4 + 8*256*4;
    cudaFuncSetAttribute(attn_kernel, cudaFuncAttributeMaxDynamicSharedMemorySize, attnSmem);
    const int gemmSmem = (2*A_BUF_F32 + 2*B_BUF_F32) * 4;   // 67584 B
    cudaFuncSetAttribute(tf32gemm_kernel, cudaFuncAttributeMaxDynamicSharedMemorySize, gemmSmem);

    // QKV projections
    tf32gemm_kernel<<<dim3(DMODEL/128,   MTOT/128), 256, gemmSmem>>>(x, Wq,  bq,  q,  MTOT, DMODEL,   DMODEL);
    tf32gemm_kernel<<<dim3(2*DMODEL/128, MTOT/128), 256, gemmSmem>>>(x, Wkv, bkv, kv, MTOT, 2*DMODEL, DMODEL);

    // sparse attention
    attn_kernel<<<dim3(SEQ/AROWS, BSZ*NH), 256, attnSmem>>>(q, kv, o);

    // output projection + residual + rmsnorm
    tf32gemm_kernel<<<dim3(DMODEL/128, MTOT/128), 256, gemmSmem>>>(o, Wo, bo, att, MTOT, DMODEL, DMODEL);
    rms_add_kernel<<<MTOT, 128>>>(x, att, rmsw, hbuf);

    // SwiGLU FFN
    tf32gemm_kernel<<<dim3(INNER_DIM/128, MTOT/128), 256, gemmSmem>>>(hbuf, l1, nullptr, u1, MTOT, INNER_DIM, DMODEL);
    tf32gemm_kernel<<<dim3(INNER_DIM/128, MTOT/128), 256, gemmSmem>>>(hbuf, l2, nullptr, u2, MTOT, INNER_DIM, DMODEL);
    silu_mul_kernel<<<(MTOT*INNER_DIM/4 + 255)/256, 256>>>(u1, u2, gate, MTOT*INNER_DIM/4);
    tf32gemm_kernel<<<dim3(DMODEL/128, MTOT/128), 256, gemmSmem>>>(gate, l3, nullptr, ffn, MTOT, DMODEL, INNER_DIM);

    // instance norm over sequence
    in1_kernel<<<dim3(32, BSZ), 256>>>(hbuf, ffn, y, ps, pq);
    in2_kernel<<<BSZ, DMODEL>>>(ps, pq, mn, rs);
    in3_kernel<<<(MTOT*DMODEL + 255)/256, 256>>>(y, mn, rs, inw, inb, out);
}

// round 7
// speedup vs baseline: 3.3427x; 1.0394x over previous
#include <cuda_runtime.h>
#include <math.h>

#define BSZ 4
#define SEQ 1024
#define DMODEL 512
#define NH 8
#define DHD 64
#define INNER_DIM 1536
#define MTOT (BSZ*SEQ)   /* 4096 */

// ---------------- scratch (device globals; no runtime allocation) ----------------
__device__ float g_q   [MTOT*DMODEL];
__device__ float g_kv  [MTOT*2*DMODEL];
__device__ float g_o   [MTOT*DMODEL];
__device__ float g_att [MTOT*DMODEL];
__device__ float g_h   [MTOT*DMODEL];
__device__ float g_u1  [MTOT*INNER_DIM];
__device__ float g_u2  [MTOT*INNER_DIM];
__device__ float g_gate[MTOT*INNER_DIM];
__device__ float g_ffn [MTOT*DMODEL];
__device__ float g_y   [MTOT*DMODEL];
__device__ float g_psum[BSZ*32*DMODEL];
__device__ float g_psq [BSZ*32*DMODEL];
__device__ float g_mean[BSZ*DMODEL];
__device__ float g_rstd[BSZ*DMODEL];
__device__ float g_sc  [(size_t)BSZ*NH*SEQ*SEQ];   /* 134MB score/coef matrix */
__device__ float g_sinv[BSZ*NH*SEQ];

// ---------------- helpers ----------------
__device__ __forceinline__ unsigned f2key(float f) {
    unsigned u = __float_as_uint(f);
    return (u & 0x80000000u) ? ~u : (u | 0x80000000u);
}
__device__ __forceinline__ float key2f(unsigned k) {
    unsigned u = (k & 0x80000000u) ? (k & 0x7fffffffu) : ~k;
    return __uint_as_float(u);
}
__device__ __forceinline__ float warpMax(float v) {
    #pragma unroll
    for (int o = 16; o; o >>= 1) v = fmaxf(v, __shfl_xor_sync(0xffffffffu, v, o));
    return v;
}
__device__ __forceinline__ float warpSum(float v) {
    #pragma unroll
    for (int o = 16; o; o >>= 1) v += __shfl_xor_sync(0xffffffffu, v, o);
    return v;
}
__device__ __forceinline__ unsigned to_tf32(float x) {
    unsigned u;
    asm("cvt.rna.tf32.f32 %0, %1;" : "=r"(u) : "f"(x));
    return u;
}
__device__ __forceinline__ float4 to_tf32x4(float4 v) {
    float4 r;
    r.x = __uint_as_float(to_tf32(v.x));
    r.y = __uint_as_float(to_tf32(v.y));
    r.z = __uint_as_float(to_tf32(v.z));
    r.w = __uint_as_float(to_tf32(v.w));
    return r;
}
__device__ __forceinline__ void ldsm4(unsigned* r, unsigned saddr) {
    asm volatile("ldmatrix.sync.aligned.m8n8.x4.shared.b16 {%0,%1,%2,%3}, [%4];"
                 : "=r"(r[0]), "=r"(r[1]), "=r"(r[2]), "=r"(r[3]) : "r"(saddr));
}
__device__ __forceinline__ void mma_tf32(float* d, const unsigned* a, const unsigned* b) {
    asm volatile(
        "mma.sync.aligned.m16n8k8.row.col.f32.tf32.tf32.f32 "
        "{%0,%1,%2,%3}, {%4,%5,%6,%7}, {%8,%9}, {%0,%1,%2,%3};"
        : "+f"(d[0]), "+f"(d[1]), "+f"(d[2]), "+f"(d[3])
        : "r"(a[0]), "r"(a[1]), "r"(a[2]), "r"(a[3]), "r"(b[0]), "r"(b[1]));
}

// ---------------- TF32 tensor-core GEMM: C[M,N] = A[M,K] @ B[K,N] (+bias) ----------------
#define GBK 32
#define A_BUF_F32 4096           /* 128*32 */
#define B_STRIDE 136             /* 128 + 8 pad */
#define B_BUF_F32 (GBK*B_STRIDE) /* 4352 */

__global__ __launch_bounds__(256, 2) void tf32gemm_kernel(
    const float* __restrict__ A, const float* __restrict__ B,
    const float* __restrict__ bias, float* __restrict__ C,
    int M, int N, int K)
{
    extern __shared__ float gsm[];
    float* AsF = gsm;                    // 2 * 4096
    float* BsF = gsm + 2*A_BUF_F32;      // 2 * 4352
    const unsigned asBase = (unsigned)__cvta_generic_to_shared(AsF);

    const int tid = threadIdx.x, lane = tid & 31, wid = tid >> 5;
    const int warpM = wid & 1, warpN = wid >> 1;
    const int bm = blockIdx.y * 128, bn = blockIdx.x * 128;

    const int mbase = warpM*64 + ((lane>>3)&1)*8 + (lane&7);
    const int jhi   = lane >> 4;
    const int xorv  = lane & 7;
    const int kb    = lane & 3;
    const int nbase = warpN*32 + (lane>>2);

    float acc[4][4][4];
    #pragma unroll
    for (int mt = 0; mt < 4; ++mt)
        #pragma unroll
        for (int nt = 0; nt < 4; ++nt)
            #pragma unroll
            for (int i = 0; i < 4; ++i) acc[mt][nt][i] = 0.0f;

    const int am = tid >> 3, ak4 = tid & 7;
    const int bk = tid >> 5, bn4 = tid & 31;

    float4 regA[4], regB[4];
    #pragma unroll
    for (int p = 0; p < 4; ++p)
        regA[p] = *(const float4*)(A + (size_t)(bm + am + p*32)*K + ak4*4);
    #pragma unroll
    for (int p = 0; p < 4; ++p)
        regB[p] = *(const float4*)(B + (size_t)(bk + p*8)*N + bn + bn4*4);
    #pragma unroll
    for (int p = 0; p < 4; ++p) {
        int m = am + p*32;
        int unit = m*8 + (ak4 ^ (m & 7));
        *(float4*)(AsF + unit*4) = to_tf32x4(regA[p]);
    }
    #pragma unroll
    for (int p = 0; p < 4; ++p)
        *(float4*)(BsF + (bk + p*8)*B_STRIDE + bn4*4) = to_tf32x4(regB[p]);
    __syncthreads();

    const int nIter = K / GBK;
    int buf = 0;
    for (int kt = 0; kt < nIter; ++kt) {
        bool more = (kt + 1 < nIter);
        if (more) {
            int k0 = (kt+1)*GBK;
            #pragma unroll
            for (int p = 0; p < 4; ++p)
                regA[p] = *(const float4*)(A + (size_t)(bm + am + p*32)*K + k0 + ak4*4);
            #pragma unroll
            for (int p = 0; p < 4; ++p)
                regB[p] = *(const float4*)(B + (size_t)(k0 + bk + p*8)*N + bn + bn4*4);
        }

        const unsigned aBufBase = asBase + buf*(A_BUF_F32*4);
        const float* bb = BsF + buf*B_BUF_F32;
        #pragma unroll
        for (int ks = 0; ks < 4; ++ks) {
            unsigned af[4][4];
            #pragma unroll
            for (int mt = 0; mt < 4; ++mt) {
                int m = mbase + mt*16;
                int unit = m*8 + ((ks*2 + jhi) ^ xorv);
                ldsm4(af[mt], aBufBase + unit*16);
            }
            unsigned bf[4][2];
            #pragma unroll
            for (int nt = 0; nt < 4; ++nt) {
                bf[nt][0] = __float_as_uint(bb[(ks*8 + kb    )*B_STRIDE + nbase + nt*8]);
                bf[nt][1] = __float_as_uint(bb[(ks*8 + kb + 4)*B_STRIDE + nbase + nt*8]);
            }
            #pragma unroll
            for (int mt = 0; mt < 4; ++mt)
                #pragma unroll
                for (int nt = 0; nt < 4; ++nt)
                    mma_tf32(acc[mt][nt], af[mt], bf[nt]);
        }

        if (more) {
            int nb = buf ^ 1;
            float* AsW = AsF + nb*A_BUF_F32;
            float* BsW = BsF + nb*B_BUF_F32;
            #pragma unroll
            for (int p = 0; p < 4; ++p) {
                int m = am + p*32;
                int unit = m*8 + (ak4 ^ (m & 7));
                *(float4*)(AsW + unit*4) = to_tf32x4(regA[p]);
            }
            #pragma unroll
            for (int p = 0; p < 4; ++p)
                *(float4*)(BsW + (bk + p*8)*B_STRIDE + bn4*4) = to_tf32x4(regB[p]);
        }
        __syncthreads();
        buf ^= 1;
    }

    const int gr = lane >> 2, gc = (lane & 3) * 2;
    #pragma unroll
    for (int nt = 0; nt < 4; ++nt) {
        int col = bn + warpN*32 + nt*8 + gc;
        float b0v = bias ? bias[col]   : 0.0f;
        float b1v = bias ? bias[col+1] : 0.0f;
        #pragma unroll
        for (int mt = 0; mt < 4; ++mt) {
            int row = bm + warpM*64 + mt*16 + gr;
            float2 v0 = make_float2(acc[mt][nt][0] + b0v, acc[mt][nt][1] + b1v);
            float2 v1 = make_float2(acc[mt][nt][2] + b0v, acc[mt][nt][3] + b1v);
            *(float2*)(C + (size_t)row*N + col)     = v0;
            *(float2*)(C + (size_t)(row+8)*N + col) = v1;
        }
    }
}

// ---------------- attention stage 1: scores S[bh,i,t] = (q_i . k_t)/8 ----------------
// grid (SEQ/128 t-tiles, SEQ/128 i-tiles, BSZ*NH), 256 threads
#define SST 68
__global__ __launch_bounds__(256) void scores_kernel(
    const float* __restrict__ qb, const float* __restrict__ kvb, float* __restrict__ scb)
{
    extern __shared__ float smem[];
    float* sQ = smem;            // 128*SST
    float* sK = smem + 128*SST;  // 128*SST
    const int tid = threadIdx.x, lane = tid & 31, wid = tid >> 5;
    const int bh = blockIdx.z, b = bh >> 3, h = bh & 7;
    const int i0 = blockIdx.y * 128, t0 = blockIdx.x * 128;

    #pragma unroll
    for (int p = 0; p < 8; ++p) {
        int idx = tid + p*256;
        int row = idx >> 4, c4 = (idx & 15) << 2;
        *(float4*)(sQ + row*SST + c4) =
            to_tf32x4(*(const float4*)(qb + (size_t)(b*SEQ + i0 + row)*DMODEL + h*DHD + c4));
    }
    #pragma unroll
    for (int p = 0; p < 8; ++p) {
        int idx = tid + p*256;
        int row = idx >> 4, c4 = (idx & 15) << 2;
        *(float4*)(sK + row*SST + c4) =
            to_tf32x4(*(const float4*)(kvb + (size_t)(b*SEQ + t0 + row)*(2*DMODEL) + h*DHD + c4));
    }
    __syncthreads();

    const int warpM = wid & 1, warpN = wid >> 1;   // 2 x 4 warps -> warp tile 64i x 32t
    const int g = lane >> 2, fb = lane & 3;

    float acc[4][4][4];
    #pragma unroll
    for (int mt = 0; mt < 4; ++mt)
        #pragma unroll
        for (int nt = 0; nt < 4; ++nt)
            #pragma unroll
            for (int i = 0; i < 4; ++i) acc[mt][nt][i] = 0.0f;

    #pragma unroll
    for (int ks = 0; ks < 8; ++ks) {
        unsigned af[4][4], bf[4][2];
        #pragma unroll
        for (int mt = 0; mt < 4; ++mt) {
            const float* ap = sQ + (warpM*64 + mt*16 + g)*SST + ks*8 + fb;
            af[mt][0] = __float_as_uint(ap[0]);
            af[mt][1] = __float_as_uint(ap[8*SST]);
            af[mt][2] = __float_as_uint(ap[4]);
            af[mt][3] = __float_as_uint(ap[8*SST + 4]);
        }
        #pragma unroll
        for (int nt = 0; nt < 4; ++nt) {
            const float* bp = sK + (warpN*32 + nt*8 + g)*SST + ks*8 + fb;
            bf[nt][0] = __float_as_uint(bp[0]);
            bf[nt][1] = __float_as_uint(bp[4]);
        }
        #pragma unroll
        for (int mt = 0; mt < 4; ++mt)
            #pragma unroll
            for (int nt = 0; nt < 4; ++nt)
                mma_tf32(acc[mt][nt], af[mt], bf[nt]);
    }

    #pragma unroll
    for (int mt = 0; mt < 4; ++mt) {
        int iLo = i0 + warpM*64 + mt*16 + g;
        #pragma unroll
        for (int nt = 0; nt < 4; ++nt) {
            int t = t0 + warpN*32 + nt*8 + 2*fb;
            *(float2*)(scb + ((size_t)bh*SEQ + iLo)*SEQ + t) =
                make_float2(acc[mt][nt][0]*0.125f, acc[mt][nt][1]*0.125f);
            *(float2*)(scb + ((size_t)bh*SEQ + iLo + 8)*SEQ + t) =
                make_float2(acc[mt][nt][2]*0.125f, acc[mt][nt][3]*0.125f);
        }
    }
}

// ---------------- attention stage 2: per-row softmax + top-512 + coef rewrite ----------------
// 1 warp per row, 8 rows per block; grid = 32768/8 = 4096
__global__ __launch_bounds__(256) void select_kernel(
    float* __restrict__ scb, float* __restrict__ sinvb)
{
    __shared__ int hist[8*256];
    const int tid = threadIdx.x, lane = tid & 31, wid = tid >> 5;
    const int r = blockIdx.x*8 + wid;
    float* row = scb + (size_t)r*SEQ;
    int* wh = hist + wid*256;

    // load entire row into registers: element (j,e) is t = (j*32+lane)*4 + e
    float4 v[8];
    #pragma unroll
    for (int j = 0; j < 8; ++j) v[j] = *(const float4*)(row + (j*32 + lane)*4);

    float m = -3.4e38f;
    #pragma unroll
    for (int j = 0; j < 8; ++j)
        m = fmaxf(m, fmaxf(fmaxf(v[j].x, v[j].y), fmaxf(v[j].z, v[j].w)));
    m = warpMax(m);
    float z1 = 0.f;
    #pragma unroll
    for (int j = 0; j < 8; ++j)
        z1 += __expf(v[j].x - m) + __expf(v[j].y - m) + __expf(v[j].z - m) + __expf(v[j].w - m);
    z1 = warpSum(z1);
    const float invZ1 = 1.0f / z1;

    // MSB radix select (4x8-bit), match_any histogram
    unsigned prefix = 0;
    int k = SEQ/2;
    #pragma unroll
    for (int shift = 24; shift >= 0; shift -= 8) {
        unsigned mask = (shift < 24) ? (0xffffffffu << (shift + 8)) : 0u;
        #pragma unroll
        for (int i = 0; i < 8; ++i) wh[lane*8 + i] = 0;
        __syncwarp();
        #pragma unroll
        for (int j = 0; j < 8; ++j) {
            const float* e4 = (const float*)&v[j];
            #pragma unroll
            for (int e = 0; e < 4; ++e) {
                unsigned key = f2key(e4[e]);
                bool ok = ((key ^ prefix) & mask) == 0u;
                unsigned digit = ok ? ((key >> shift) & 255u) : 0xffffffffu;
                unsigned grp = __match_any_sync(0xffffffffu, digit);
                bool leader = ((int)__ffs(grp) - 1) == lane;
                if (ok && leader) wh[digit] += __popc(grp);
            }
        }
        __syncwarp();
        int h8[8]; int vv = 0;
        #pragma unroll
        for (int i = 0; i < 8; ++i) { h8[i] = wh[lane*8 + i]; vv += h8[i]; }
        int inc = vv;
        #pragma unroll
        for (int o = 1; o < 32; o <<= 1) {
            int tt = __shfl_down_sync(0xffffffffu, inc, o);
            if (lane + o < 32) inc += tt;
        }
        int above = inc - vv;
        int sel = -1, newk = 0;
        if (above < k && inc >= k) {
            int csum = above;
            #pragma unroll
            for (int j = 7; j >= 0; --j) {
                int hc = h8[j];
                if (csum + hc >= k) { sel = lane*8 + j; newk = k - csum; break; }
                csum += hc;
            }
        }
        unsigned bal = __ballot_sync(0xffffffffu, sel >= 0);
        int srcl = __ffs(bal) - 1;
        sel = __shfl_sync(0xffffffffu, sel, srcl);
        k   = __shfl_sync(0xffffffffu, newk, srcl);
        prefix |= ((unsigned)sel) << shift;
    }
    const unsigned tauKey = prefix;
    const int needEq = k;

    // coefficient rewrite in registers; collect equal-to-tau indices
    if (lane == 0) wh[0] = 0;
    __syncwarp();
    float z2 = 0.f;
    unsigned eqmask = 0;
    #pragma unroll
    for (int j = 0; j < 8; ++j) {
        float* e4 = (float*)&v[j];
        #pragma unroll
        for (int e = 0; e < 4; ++e) {
            float s = e4[e];
            unsigned key = f2key(s);
            float coef = 1.0f;
            if (key > tauKey) {
                coef = __uint_as_float(to_tf32(__expf(__expf(s - m) * invZ1)));
            } else if (key == tauKey) {
                int p = atomicAdd(&wh[0], 1);
                if (p < 255) wh[1 + p] = (j*32 + lane)*4 + e;
                eqmask |= 1u << (j*4 + e);
            }
            e4[e] = coef;
            z2 += coef;
        }
    }
    __syncwarp();
    z2 = warpSum(z2);
    int neq = wh[0];
    int listN = neq < 255 ? neq : 255;
    float ctau = __uint_as_float(to_tf32(__expf(__expf(key2f(tauKey) - m) * invZ1)));

    // each lane resolves ranks of its own equal elements (jax tie rule: earliest t kept)
    if (eqmask) {
        #pragma unroll
        for (int j = 0; j < 8; ++j) {
            float* e4 = (float*)&v[j];
            #pragma unroll
            for (int e = 0; e < 4; ++e) {
                if (eqmask & (1u << (j*4 + e))) {
                    int t = (j*32 + lane)*4 + e;
                    int rank = 0;
                    for (int q = 0; q < listN; ++q) rank += (wh[1 + q] < t);
                    if (rank < needEq) e4[e] = ctau;
                }
            }
        }
    }
    int keptEq = needEq < neq ? needEq : neq;
    z2 += (ctau - 1.0f) * (float)keptEq;

    #pragma unroll
    for (int j = 0; j < 8; ++j) *(float4*)(row + (j*32 + lane)*4) = v[j];
    if (lane == 0) sinvb[r] = 1.0f / z2;
}

// ---------------- attention stage 3: O[bh] = diag(1/Z2) * W @ V ----------------
// grid (SEQ/64 i-tiles, BSZ*NH), 256 threads; tile 64i x 64dh, k-chunks of 64
#define AWST 68
#define AVST 72
__global__ __launch_bounds__(256) void av_kernel(
    const float* __restrict__ scb, const float* __restrict__ kvb,
    const float* __restrict__ sinvb, float* __restrict__ ob)
{
    __shared__ float sW[64*AWST];
    __shared__ float sV[64*AVST];
    const int tid = threadIdx.x, lane = tid & 31, wid = tid >> 5;
    const int bh = blockIdx.y, b = bh >> 3, h = bh & 7;
    const int i0 = blockIdx.x * 64;
    const int warpM = wid & 1, warpN = wid >> 1;   // warp tile 32i x 16dh
    const int g = lane >> 2, fb = lane & 3;

    float acc[2][2][4];
    #pragma unroll
    for (int mt = 0; mt < 2; ++mt)
        #pragma unroll
        for (int nt = 0; nt < 2; ++nt)
            #pragma unroll
            for (int i = 0; i < 4; ++i) acc[mt][nt][i] = 0.0f;

    for (int c = 0; c < SEQ/64; ++c) {
        __syncthreads();
        #pragma unroll
        for (int p = 0; p < 4; ++p) {
            int idx = tid + p*256;
            int rowi = idx >> 4, c4 = (idx & 15) << 2;
            *(float4*)(sW + rowi*AWST + c4) =
                *(const float4*)(scb + ((size_t)bh*SEQ + i0 + rowi)*SEQ + c*64 + c4);
        }
        #pragma unroll
        for (int p = 0; p < 4; ++p) {
            int idx = tid + p*256;
            int rowt = idx >> 4, c4 = (idx & 15) << 2;
            *(float4*)(sV + rowt*AVST + c4) =
                to_tf32x4(*(const float4*)(kvb + (size_t)(b*SEQ + c*64 + rowt)*(2*DMODEL) + DMODEL + h*DHD + c4));
        }
        __syncthreads();

        #pragma unroll
        for (int ks = 0; ks < 8; ++ks) {
            unsigned af[2][4], bf[2][2];
            #pragma unroll
            for (int mt = 0; mt < 2; ++mt) {
                const float* ap = sW + (warpM*32 + mt*16 + g)*AWST + ks*8 + fb;
                af[mt][0] = __float_as_uint(ap[0]);
                af[mt][1] = __float_as_uint(ap[8*AWST]);
                af[mt][2] = __float_as_uint(ap[4]);
                af[mt][3] = __float_as_uint(ap[8*AWST + 4]);
            }
            #pragma unroll
            for (int nt = 0; nt < 2; ++nt) {
                const float* bp = sV + (ks*8 + fb)*AVST + warpN*16 + nt*8 + g;
                bf[nt][0] = __float_as_uint(bp[0]);
                bf[nt][1] = __float_as_uint(bp[4*AVST]);
            }
            #pragma unroll
            for (int mt = 0; mt < 2; ++mt)
                #pragma unroll
                for (int nt = 0; nt < 2; ++nt)
                    mma_tf32(acc[mt][nt], af[mt], bf[nt]);
        }
    }

    #pragma unroll
    for (int mt = 0; mt < 2; ++mt) {
        int iLo = i0 + warpM*32 + mt*16 + g;
        int iHi = iLo + 8;
        float zLo = sinvb[bh*SEQ + iLo];
        float zHi = sinvb[bh*SEQ + iHi];
        #pragma unroll
        for (int nt = 0; nt < 2; ++nt) {
            int col = h*DHD + warpN*16 + nt*8 + 2*fb;
            *(float2*)(ob + (size_t)(b*SEQ + iLo)*DMODEL + col) =
                make_float2(acc[mt][nt][0]*zLo, acc[mt][nt][1]*zLo);
            *(float2*)(ob + (size_t)(b*SEQ + iHi)*DMODEL + col) =
                make_float2(acc[mt][nt][2]*zHi, acc[mt][nt][3]*zHi);
        }
    }
}

// ---------------- residual + RMSNorm (per row of 512) ----------------
__global__ __launch_bounds__(128) void rms_add_kernel(
    const float* __restrict__ x, const float* __restrict__ a,
    const float* __restrict__ w, float* __restrict__ out)
{
    __shared__ float red[4];
    int row = blockIdx.x;
    int t = threadIdx.x;
    const float4* x4 = (const float4*)(x + (size_t)row*DMODEL);
    const float4* a4 = (const float4*)(a + (size_t)row*DMODEL);
    float4 xv = x4[t], av = a4[t];
    float4 s = make_float4(xv.x+av.x, xv.y+av.y, xv.z+av.z, xv.w+av.w);
    float ss = s.x*s.x + s.y*s.y + s.z*s.z + s.w*s.w;
    ss = warpSum(ss);
    if ((t & 31) == 0) red[t >> 5] = ss;
    __syncthreads();
    float tot = red[0] + red[1] + red[2] + red[3];
    float inv = rsqrtf(tot * (1.0f/DMODEL) + 1e-6f);
    float4 wv = ((const float4*)w)[t];
    float4 o = make_float4(s.x*inv*wv.x, s.y*inv*wv.y, s.z*inv*wv.z, s.w*inv*wv.w);
    ((float4*)(out + (size_t)row*DMODEL))[t] = o;
}

// ---------------- silu(u1)*u2 ----------------
__global__ void silu_mul_kernel(const float* __restrict__ u1, const float* __restrict__ u2,
                                float* __restrict__ g, int n4)
{
    int i = blockIdx.x*blockDim.x + threadIdx.x;
    if (i < n4) {
        float4 a = ((const float4*)u1)[i];
        float4 bb = ((const float4*)u2)[i];
        float4 r;
        r.x = a.x / (1.f + __expf(-a.x)) * bb.x;
        r.y = a.y / (1.f + __expf(-a.y)) * bb.y;
        r.z = a.z / (1.f + __expf(-a.z)) * bb.z;
        r.w = a.w / (1.f + __expf(-a.w)) * bb.w;
        ((float4*)g)[i] = r;
    }
}

// ---------------- instance norm over sequence dim ----------------
__global__ __launch_bounds__(256) void in1_kernel(
    const float* __restrict__ hh, const float* __restrict__ ffn,
    float* __restrict__ y, float* __restrict__ psum, float* __restrict__ psq)
{
    int b = blockIdx.y, chunk = blockIdx.x;
    int s0 = chunk * 32;
    int t = threadIdx.x;
    float s_[2] = {0.f, 0.f}, q_[2] = {0.f, 0.f};
    for (int s = 0; s < 32; ++s) {
        size_t base = ((size_t)(b*SEQ + s0 + s))*DMODEL;
        #pragma unroll
        for (int u = 0; u < 2; ++u) {
            int d = t + u*256;
            float yv = hh[base + d] + ffn[base + d];
            y[base + d] = yv;
            s_[u] += yv; q_[u] += yv*yv;
        }
    }
    #pragma unroll
    for (int u = 0; u < 2; ++u) {
        size_t pidx = ((size_t)b*32 + chunk)*DMODEL + t + u*256;
        psum[pidx] = s_[u];
        psq [pidx] = q_[u];
    }
}

__global__ void in2_kernel(const float* __restrict__ psum, const float* __restrict__ psq,
                           float* __restrict__ mean, float* __restrict__ rstd)
{
    int b = blockIdx.x, d = threadIdx.x;
    float s = 0.f, q = 0.f;
    for (int c = 0; c < 32; ++c) {
        size_t pidx = ((size_t)b*32 + c)*DMODEL + d;
        s += psum[pidx]; q += psq[pidx];
    }
    float m = s * (1.0f/SEQ);
    float v = q * (1.0f/SEQ) - m*m;
    mean[b*DMODEL + d] = m;
    rstd[b*DMODEL + d] = rsqrtf(v + 1e-5f);
}

__global__ void in3_kernel(const float* __restrict__ y, const float* __restrict__ mean,
                           const float* __restrict__ rstd, const float* __restrict__ w,
                           const float* __restrict__ bb, float* __restrict__ out)
{
    int i = blockIdx.x*blockDim.x + threadIdx.x;
    if (i < MTOT*DMODEL) {
        int d = i & (DMODEL - 1);
        int b = i >> 19;  // SEQ*DMODEL = 2^19
        float m = mean[b*DMODEL + d], r = rstd[b*DMODEL + d];
        out[i] = (y[i] - m) * r * w[d] + bb[d];
    }
}

// ---------------- launch ----------------
extern "C" void kernel_launch(void* const* d_in, const int* in_sizes, int n_in,
                              void* d_out, int out_size)
{
    (void)in_sizes; (void)n_in; (void)out_size;
    const float* x    = (const float*)d_in[0];
    const float* Wq   = (const float*)d_in[1];
    const float* bq   = (const float*)d_in[2];
    const float* Wkv  = (const float*)d_in[3];
    const float* bkv  = (const float*)d_in[4];
    const float* Wo   = (const float*)d_in[5];
    const float* bo   = (const float*)d_in[6];
    const float* rmsw = (const float*)d_in[7];
    const float* l1   = (const float*)d_in[8];
    const float* l2   = (const float*)d_in[9];
    const float* l3   = (const float*)d_in[10];
    const float* inw  = (const float*)d_in[11];
    const float* inb  = (const float*)d_in[12];
    float* out = (float*)d_out;

    float *q, *kv, *o, *att, *hbuf, *u1, *u2, *gate, *ffn, *y, *ps, *pq, *mn, *rs, *sc, *sv;
    cudaGetSymbolAddress((void**)&q,    g_q);
    cudaGetSymbolAddress((void**)&kv,   g_kv);
    cudaGetSymbolAddress((void**)&o,    g_o);
    cudaGetSymbolAddress((void**)&att,  g_att);
    cudaGetSymbolAddress((void**)&hbuf, g_h);
    cudaGetSymbolAddress((void**)&u1,   g_u1);
    cudaGetSymbolAddress((void**)&u2,   g_u2);
    cudaGetSymbolAddress((void**)&gate, g_gate);
    cudaGetSymbolAddress((void**)&ffn,  g_ffn);
    cudaGetSymbolAddress((void**)&y,    g_y);
    cudaGetSymbolAddress((void**)&ps,   g_psum);
    cudaGetSymbolAddress((void**)&pq,   g_psq);
    cudaGetSymbolAddress((void**)&mn,   g_mean);
    cudaGetSymbolAddress((void**)&rs,   g_rstd);
    cudaGetSymbolAddress((void**)&sc,   g_sc);
    cudaGetSymbolAddress((void**)&sv,   g_sinv);

    const int gemmSmem = (2*A_BUF_F32 + 2*B_BUF_F32) * 4;   // 67584 B
    cudaFuncSetAttribute(tf32gemm_kernel, cudaFuncAttributeMaxDynamicSharedMemorySize, gemmSmem);
    const int scoresSmem = 2*128*SST*4;                      // 69632 B
    cudaFuncSetAttribute(scores_kernel, cudaFuncAttributeMaxDynamicSharedMemorySize, scoresSmem);

    // QKV projections
    tf32gemm_kernel<<<dim3(DMODEL/128,   MTOT/128), 256, gemmSmem>>>(x, Wq,  bq,  q,  MTOT, DMODEL,   DMODEL);
    tf32gemm_kernel<<<dim3(2*DMODEL/128, MTOT/128), 256, gemmSmem>>>(x, Wkv, bkv, kv, MTOT, 2*DMODEL, DMODEL);

    // sparse attention: scores -> select -> AV
    scores_kernel<<<dim3(SEQ/128, SEQ/128, BSZ*NH), 256, scoresSmem>>>(q, kv, sc);
    select_kernel<<<BSZ*NH*SEQ/8, 256>>>(sc, sv);
    av_kernel<<<dim3(SEQ/64, BSZ*NH), 256>>>(sc, kv, sv, o);

    // output projection + residual + rmsnorm
    tf32gemm_kernel<<<dim3(DMODEL/128, MTOT/128), 256, gemmSmem>>>(o, Wo, bo, att, MTOT, DMODEL, DMODEL);
    rms_add_kernel<<<MTOT, 128>>>(x, att, rmsw, hbuf);

    // SwiGLU FFN
    tf32gemm_kernel<<<dim3(INNER_DIM/128, MTOT/128), 256, gemmSmem>>>(hbuf, l1, nullptr, u1, MTOT, INNER_DIM, DMODEL);
    tf32gemm_kernel<<<dim3(INNER_DIM/128, MTOT/128), 256, gemmSmem>>>(hbuf, l2, nullptr, u2, MTOT, INNER_DIM, DMODEL);
    silu_mul_kernel<<<(MTOT*INNER_DIM/4 + 255)/256, 256>>>(u1, u2, gate, MTOT*INNER_DIM/4);
    tf32gemm_kernel<<<dim3(DMODEL/128, MTOT/128), 256, gemmSmem>>>(gate, l3, nullptr, ffn, MTOT, DMODEL, INNER_DIM);

    // instance norm over sequence
    in1_kernel<<<dim3(32, BSZ), 256>>>(hbuf, ffn, y, ps, pq);
    in2_kernel<<<BSZ, DMODEL>>>(ps, pq, mn, rs);
    in3_kernel<<<(MTOT*DMODEL + 255)/256, 256>>>(y, mn, rs, inw, inb, out);
}

// round 9
// speedup vs baseline: 5.9108x; 1.7683x over previous
#include <cuda_runtime.h>
#include <math.h>

#define BSZ 4
#define SEQ 1024
#define DMODEL 512
#define NH 8
#define DHD 64
#define INNER_DIM 1536
#define MTOT (BSZ*SEQ)   /* 4096 */

// ---------------- scratch (device globals; no runtime allocation) ----------------
__device__ float g_q   [MTOT*DMODEL];
__device__ float g_kv  [MTOT*2*DMODEL];
__device__ float g_o   [MTOT*DMODEL];
__device__ float g_att [MTOT*DMODEL];
__device__ float g_h   [MTOT*DMODEL];
__device__ float g_u1  [MTOT*INNER_DIM];
__device__ float g_u2  [MTOT*INNER_DIM];
__device__ float g_gate[MTOT*INNER_DIM];
__device__ float g_ffn [MTOT*DMODEL];
__device__ float g_y   [MTOT*DMODEL];
__device__ float g_psum[BSZ*32*DMODEL];
__device__ float g_psq [BSZ*32*DMODEL];
__device__ float g_mean[BSZ*DMODEL];
__device__ float g_rstd[BSZ*DMODEL];
__device__ float g_sc  [(size_t)BSZ*NH*SEQ*SEQ];   /* 134MB score/coef matrix */
__device__ float g_sinv[BSZ*NH*SEQ];

// ---------------- helpers ----------------
__device__ __forceinline__ unsigned f2key(float f) {
    unsigned u = __float_as_uint(f);
    return (u & 0x80000000u) ? ~u : (u | 0x80000000u);
}
__device__ __forceinline__ float key2f(unsigned k) {
    unsigned u = (k & 0x80000000u) ? (k & 0x7fffffffu) : ~k;
    return __uint_as_float(u);
}
__device__ __forceinline__ float warpMax(float v) {
    #pragma unroll
    for (int o = 16; o; o >>= 1) v = fmaxf(v, __shfl_xor_sync(0xffffffffu, v, o));
    return v;
}
__device__ __forceinline__ unsigned warpMaxU(unsigned v) {
    #pragma unroll
    for (int o = 16; o; o >>= 1) v = umax(v, __shfl_xor_sync(0xffffffffu, v, o));
    return v;
}
__device__ __forceinline__ int warpMaxI(int v) {
    #pragma unroll
    for (int o = 16; o; o >>= 1) v = max(v, __shfl_xor_sync(0xffffffffu, v, o));
    return v;
}
__device__ __forceinline__ float warpSum(float v) {
    #pragma unroll
    for (int o = 16; o; o >>= 1) v += __shfl_xor_sync(0xffffffffu, v, o);
    return v;
}
__device__ __forceinline__ unsigned to_tf32(float x) {
    unsigned u;
    asm("cvt.rna.tf32.f32 %0, %1;" : "=r"(u) : "f"(x));
    return u;
}
__device__ __forceinline__ float4 to_tf32x4(float4 v) {
    float4 r;
    r.x = __uint_as_float(to_tf32(v.x));
    r.y = __uint_as_float(to_tf32(v.y));
    r.z = __uint_as_float(to_tf32(v.z));
    r.w = __uint_as_float(to_tf32(v.w));
    return r;
}
__device__ __forceinline__ void ldsm4(unsigned* r, unsigned saddr) {
    asm volatile("ldmatrix.sync.aligned.m8n8.x4.shared.b16 {%0,%1,%2,%3}, [%4];"
                 : "=r"(r[0]), "=r"(r[1]), "=r"(r[2]), "=r"(r[3]) : "r"(saddr));
}
__device__ __forceinline__ void mma_tf32(float* d, const unsigned* a, const unsigned* b) {
    asm volatile(
        "mma.sync.aligned.m16n8k8.row.col.f32.tf32.tf32.f32 "
        "{%0,%1,%2,%3}, {%4,%5,%6,%7}, {%8,%9}, {%0,%1,%2,%3};"
        : "+f"(d[0]), "+f"(d[1]), "+f"(d[2]), "+f"(d[3])
        : "r"(a[0]), "r"(a[1]), "r"(a[2]), "r"(a[3]), "r"(b[0]), "r"(b[1]));
}

// ---------------- TF32 tensor-core GEMM: C[M,N] = A[M,K] @ B[K,N] (+bias) ----------------
#define GBK 32
#define A_BUF_F32 4096           /* 128*32 */
#define B_STRIDE 136             /* 128 + 8 pad */
#define B_BUF_F32 (GBK*B_STRIDE) /* 4352 */

__global__ __launch_bounds__(256, 2) void tf32gemm_kernel(
    const float* __restrict__ A, const float* __restrict__ B,
    const float* __restrict__ bias, float* __restrict__ C,
    int M, int N, int K)
{
    extern __shared__ float gsm[];
    float* AsF = gsm;                    // 2 * 4096
    float* BsF = gsm + 2*A_BUF_F32;      // 2 * 4352
    const unsigned asBase = (unsigned)__cvta_generic_to_shared(AsF);

    const int tid = threadIdx.x, lane = tid & 31, wid = tid >> 5;
    const int warpM = wid & 1, warpN = wid >> 1;
    const int bm = blockIdx.y * 128, bn = blockIdx.x * 128;

    const int mbase = warpM*64 + ((lane>>3)&1)*8 + (lane&7);
    const int jhi   = lane >> 4;
    const int xorv  = lane & 7;
    const int kb    = lane & 3;
    const int nbase = warpN*32 + (lane>>2);

    float acc[4][4][4];
    #pragma unroll
    for (int mt = 0; mt < 4; ++mt)
        #pragma unroll
        for (int nt = 0; nt < 4; ++nt)
            #pragma unroll
            for (int i = 0; i < 4; ++i) acc[mt][nt][i] = 0.0f;

    const int am = tid >> 3, ak4 = tid & 7;
    const int bk = tid >> 5, bn4 = tid & 31;

    float4 regA[4], regB[4];
    #pragma unroll
    for (int p = 0; p < 4; ++p)
        regA[p] = *(const float4*)(A + (size_t)(bm + am + p*32)*K + ak4*4);
    #pragma unroll
    for (int p = 0; p < 4; ++p)
        regB[p] = *(const float4*)(B + (size_t)(bk + p*8)*N + bn + bn4*4);
    #pragma unroll
    for (int p = 0; p < 4; ++p) {
        int m = am + p*32;
        int unit = m*8 + (ak4 ^ (m & 7));
        *(float4*)(AsF + unit*4) = to_tf32x4(regA[p]);
    }
    #pragma unroll
    for (int p = 0; p < 4; ++p)
        *(float4*)(BsF + (bk + p*8)*B_STRIDE + bn4*4) = to_tf32x4(regB[p]);
    __syncthreads();

    const int nIter = K / GBK;
    int buf = 0;
    for (int kt = 0; kt < nIter; ++kt) {
        bool more = (kt + 1 < nIter);
        if (more) {
            int k0 = (kt+1)*GBK;
            #pragma unroll
            for (int p = 0; p < 4; ++p)
                regA[p] = *(const float4*)(A + (size_t)(bm + am + p*32)*K + k0 + ak4*4);
            #pragma unroll
            for (int p = 0; p < 4; ++p)
                regB[p] = *(const float4*)(B + (size_t)(k0 + bk + p*8)*N + bn + bn4*4);
        }

        const unsigned aBufBase = asBase + buf*(A_BUF_F32*4);
        const float* bb = BsF + buf*B_BUF_F32;
        #pragma unroll
        for (int ks = 0; ks < 4; ++ks) {
            unsigned af[4][4];
            #pragma unroll
            for (int mt = 0; mt < 4; ++mt) {
                int m = mbase + mt*16;
                int unit = m*8 + ((ks*2 + jhi) ^ xorv);
                ldsm4(af[mt], aBufBase + unit*16);
            }
            unsigned bf[4][2];
            #pragma unroll
            for (int nt = 0; nt < 4; ++nt) {
                bf[nt][0] = __float_as_uint(bb[(ks*8 + kb    )*B_STRIDE + nbase + nt*8]);
                bf[nt][1] = __float_as_uint(bb[(ks*8 + kb + 4)*B_STRIDE + nbase + nt*8]);
            }
            #pragma unroll
            for (int mt = 0; mt < 4; ++mt)
                #pragma unroll
                for (int nt = 0; nt < 4; ++nt)
                    mma_tf32(acc[mt][nt], af[mt], bf[nt]);
        }

        if (more) {
            int nb = buf ^ 1;
            float* AsW = AsF + nb*A_BUF_F32;
            float* BsW = BsF + nb*B_BUF_F32;
            #pragma unroll
            for (int p = 0; p < 4; ++p) {
                int m = am + p*32;
                int unit = m*8 + (ak4 ^ (m & 7));
                *(float4*)(AsW + unit*4) = to_tf32x4(regA[p]);
            }
            #pragma unroll
            for (int p = 0; p < 4; ++p)
                *(float4*)(BsW + (bk + p*8)*B_STRIDE + bn4*4) = to_tf32x4(regB[p]);
        }
        __syncthreads();
        buf ^= 1;
    }

    const int gr = lane >> 2, gc = (lane & 3) * 2;
    #pragma unroll
    for (int nt = 0; nt < 4; ++nt) {
        int col = bn + warpN*32 + nt*8 + gc;
        float b0v = bias ? bias[col]   : 0.0f;
        float b1v = bias ? bias[col+1] : 0.0f;
        #pragma unroll
        for (int mt = 0; mt < 4; ++mt) {
            int row = bm + warpM*64 + mt*16 + gr;
            float2 v0 = make_float2(acc[mt][nt][0] + b0v, acc[mt][nt][1] + b1v);
            float2 v1 = make_float2(acc[mt][nt][2] + b0v, acc[mt][nt][3] + b1v);
            *(float2*)(C + (size_t)row*N + col)     = v0;
            *(float2*)(C + (size_t)(row+8)*N + col) = v1;
        }
    }
}

// ---------------- attention stage 1: scores S[bh,i,t] = (q_i . k_t)/8 ----------------
// grid (SEQ/128 t-tiles, SEQ/128 i-tiles, BSZ*NH), 256 threads
#define SST 68
__global__ __launch_bounds__(256) void scores_kernel(
    const float* __restrict__ qb, const float* __restrict__ kvb, float* __restrict__ scb)
{
    extern __shared__ float smem[];
    float* sQ = smem;            // 128*SST
    float* sK = smem + 128*SST;  // 128*SST
    const int tid = threadIdx.x, lane = tid & 31, wid = tid >> 5;
    const int bh = blockIdx.z, b = bh >> 3, h = bh & 7;
    const int i0 = blockIdx.y * 128, t0 = blockIdx.x * 128;

    #pragma unroll
    for (int p = 0; p < 8; ++p) {
        int idx = tid + p*256;
        int row = idx >> 4, c4 = (idx & 15) << 2;
        *(float4*)(sQ + row*SST + c4) =
            to_tf32x4(*(const float4*)(qb + (size_t)(b*SEQ + i0 + row)*DMODEL + h*DHD + c4));
    }
    #pragma unroll
    for (int p = 0; p < 8; ++p) {
        int idx = tid + p*256;
        int row = idx >> 4, c4 = (idx & 15) << 2;
        *(float4*)(sK + row*SST + c4) =
            to_tf32x4(*(const float4*)(kvb + (size_t)(b*SEQ + t0 + row)*(2*DMODEL) + h*DHD + c4));
    }
    __syncthreads();

    const int warpM = wid & 1, warpN = wid >> 1;   // 2 x 4 warps -> warp tile 64i x 32t
    const int g = lane >> 2, fb = lane & 3;

    float acc[4][4][4];
    #pragma unroll
    for (int mt = 0; mt < 4; ++mt)
        #pragma unroll
        for (int nt = 0; nt < 4; ++nt)
            #pragma unroll
            for (int i = 0; i < 4; ++i) acc[mt][nt][i] = 0.0f;

    #pragma unroll
    for (int ks = 0; ks < 8; ++ks) {
        unsigned af[4][4], bf[4][2];
        #pragma unroll
        for (int mt = 0; mt < 4; ++mt) {
            const float* ap = sQ + (warpM*64 + mt*16 + g)*SST + ks*8 + fb;
            af[mt][0] = __float_as_uint(ap[0]);
            af[mt][1] = __float_as_uint(ap[8*SST]);
            af[mt][2] = __float_as_uint(ap[4]);
            af[mt][3] = __float_as_uint(ap[8*SST + 4]);
        }
        #pragma unroll
        for (int nt = 0; nt < 4; ++nt) {
            const float* bp = sK + (warpN*32 + nt*8 + g)*SST + ks*8 + fb;
            bf[nt][0] = __float_as_uint(bp[0]);
            bf[nt][1] = __float_as_uint(bp[4]);
        }
        #pragma unroll
        for (int mt = 0; mt < 4; ++mt)
            #pragma unroll
            for (int nt = 0; nt < 4; ++nt)
                mma_tf32(acc[mt][nt], af[mt], bf[nt]);
    }

    #pragma unroll
    for (int mt = 0; mt < 4; ++mt) {
        int iLo = i0 + warpM*64 + mt*16 + g;
        #pragma unroll
        for (int nt = 0; nt < 4; ++nt) {
            int t = t0 + warpN*32 + nt*8 + 2*fb;
            *(float2*)(scb + ((size_t)bh*SEQ + iLo)*SEQ + t) =
                make_float2(acc[mt][nt][0]*0.125f, acc[mt][nt][1]*0.125f);
            *(float2*)(scb + ((size_t)bh*SEQ + iLo + 8)*SEQ + t) =
                make_float2(acc[mt][nt][2]*0.125f, acc[mt][nt][3]*0.125f);
        }
    }
}

// ---------------- attention stage 2: per-row softmax + top-512 + coef rewrite ----------------
// 1 warp per row, 8 rows per block; keys live in smem; grid = 32768/8 = 4096
__global__ __launch_bounds__(256, 4) void select_kernel(
    float* __restrict__ scb, float* __restrict__ sinvb)
{
    __shared__ unsigned skeys[8][1024];
    __shared__ int hist[8*256];
    const int tid = threadIdx.x, lane = tid & 31, wid = tid >> 5;
    const int r = blockIdx.x*8 + wid;
    float* row = scb + (size_t)r*SEQ;
    unsigned* keys = skeys[wid];
    int* wh = hist + wid*256;

    // load scores -> keys (order-preserving); row max from key max
    unsigned mk = 0;
    #pragma unroll
    for (int j = 0; j < 32; ++j) {
        unsigned key = f2key(row[j*32 + lane]);
        keys[j*32 + lane] = key;
        mk = umax(mk, key);
    }
    mk = warpMaxU(mk);
    const float m = key2f(mk);
    __syncwarp();
    float z1 = 0.f;
    #pragma unroll
    for (int j = 0; j < 32; ++j)
        z1 += __expf(key2f(keys[j*32 + lane]) - m);
    z1 = warpSum(z1);
    const float invZ1 = 1.0f / z1;

    // MSB radix select (4x8-bit) with alive-mask pruning
    const unsigned MASKS[4]  = {0u, 0xff000000u, 0xffff0000u, 0xffffff00u};
    const int      SHIFTS[4] = {24, 16, 8, 0};
    unsigned alive = 0xffffffffu;
    unsigned prefix = 0;
    int k = SEQ/2;
    #pragma unroll
    for (int pi = 0; pi < 4; ++pi) {
        const int shift = SHIFTS[pi];
        const unsigned maskHi = MASKS[pi];
        #pragma unroll
        for (int i = 0; i < 8; ++i) wh[lane*8 + i] = 0;
        __syncwarp();
        unsigned msk = alive;
        int mx = warpMaxI(__popc(msk));
        for (int it = 0; it < mx; ++it) {
            unsigned digit = 0xffffffffu;
            if (msk) {
                int j = __ffs(msk) - 1;
                msk &= msk - 1;
                unsigned key = keys[j*32 + lane];
                if (((key ^ prefix) & maskHi) == 0u) digit = (key >> shift) & 255u;
                else alive &= ~(1u << j);
            }
            unsigned grp = __match_any_sync(0xffffffffu, digit);
            if (digit != 0xffffffffu && ((int)__ffs(grp) - 1) == lane)
                wh[digit] += __popc(grp);
        }
        __syncwarp();
        int h8[8]; int vv = 0;
        #pragma unroll
        for (int i = 0; i < 8; ++i) { h8[i] = wh[lane*8 + i]; vv += h8[i]; }
        int inc = vv;
        #pragma unroll
        for (int o = 1; o < 32; o <<= 1) {
            int tt = __shfl_down_sync(0xffffffffu, inc, o);
            if (lane + o < 32) inc += tt;
        }
        int above = inc - vv;
        int sel = -1, newk = 0;
        if (above < k && inc >= k) {
            int csum = above;
            #pragma unroll
            for (int j = 7; j >= 0; --j) {
                int hc = h8[j];
                if (csum + hc >= k) { sel = lane*8 + j; newk = k - csum; break; }
                csum += hc;
            }
        }
        unsigned bal = __ballot_sync(0xffffffffu, sel >= 0);
        int srcl = __ffs(bal) - 1;
        sel = __shfl_sync(0xffffffffu, sel, srcl);
        k   = __shfl_sync(0xffffffffu, newk, srcl);
        prefix |= ((unsigned)sel) << shift;
        __syncwarp();
    }
    const unsigned tauKey = prefix;
    const int needEq = k;

    // collect equal-to-tau indices
    if (lane == 0) wh[0] = 0;
    __syncwarp();
    unsigned eqmask = 0;
    #pragma unroll
    for (int j = 0; j < 32; ++j) {
        if (keys[j*32 + lane] == tauKey) {
            int p = atomicAdd(&wh[0], 1);
            if (p < 255) wh[1 + p] = j*32 + lane;
            eqmask |= 1u << j;
        }
    }
    __syncwarp();
    int neq = wh[0];
    int listN = neq < 255 ? neq : 255;
    float ctau = __uint_as_float(to_tf32(__expf(__expf(key2f(tauKey) - m) * invZ1)));

    // coefficient write + Z2
    float z2 = 0.f;
    #pragma unroll
    for (int j = 0; j < 32; ++j) {
        unsigned key = keys[j*32 + lane];
        float coef = 1.0f;
        if (key > tauKey)
            coef = __uint_as_float(to_tf32(__expf(__expf(key2f(key) - m) * invZ1)));
        row[j*32 + lane] = coef;
        z2 += coef;
    }
    z2 = warpSum(z2);

    // resolve ties (jax rule: earliest t kept)
    if (eqmask) {
        unsigned em = eqmask;
        while (em) {
            int j = __ffs(em) - 1;
            em &= em - 1;
            int t = j*32 + lane;
            int rank = 0;
            for (int q = 0; q < listN; ++q) rank += (wh[1 + q] < t);
            if (rank < needEq) row[t] = ctau;
        }
    }
    int keptEq = needEq < neq ? needEq : neq;
    z2 += (ctau - 1.0f) * (float)keptEq;
    if (lane == 0) sinvb[r] = 1.0f / z2;
}

// ---------------- attention stage 3: O[bh] = diag(1/Z2) * W @ V ----------------
// grid (SEQ/64 i-tiles, BSZ*NH), 256 threads; tile 64i x 64dh, k-chunks of 64, reg prefetch
#define AWST 68
#define AVST 72
__global__ __launch_bounds__(256) void av_kernel(
    const float* __restrict__ scb, const float* __restrict__ kvb,
    const float* __restrict__ sinvb, float* __restrict__ ob)
{
    __shared__ float sW[64*AWST];
    __shared__ float sV[64*AVST];
    const int tid = threadIdx.x, lane = tid & 31, wid = tid >> 5;
    const int bh = blockIdx.y, b = bh >> 3, h = bh & 7;
    const int i0 = blockIdx.x * 64;
    const int warpM = wid & 1, warpN = wid >> 1;   // warp tile 32i x 16dh
    const int g = lane >> 2, fb = lane & 3;

    const int ldRow = tid >> 4, ldC4 = (tid & 15) << 2;   // 16 rows per pass, 4 passes

    float acc[2][2][4];
    #pragma unroll
    for (int mt = 0; mt < 2; ++mt)
        #pragma unroll
        for (int nt = 0; nt < 2; ++nt)
            #pragma unroll
            for (int i = 0; i < 4; ++i) acc[mt][nt][i] = 0.0f;

    float4 pW[4], pV[4];
    #pragma unroll
    for (int p = 0; p < 4; ++p) {
        int rowi = ldRow + p*16;
        pW[p] = *(const float4*)(scb + ((size_t)bh*SEQ + i0 + rowi)*SEQ + ldC4);
        pV[p] = to_tf32x4(*(const float4*)(kvb + (size_t)(b*SEQ + rowi)*(2*DMODEL) + DMODEL + h*DHD + ldC4));
    }

    for (int c = 0; c < SEQ/64; ++c) {
        #pragma unroll
        for (int p = 0; p < 4; ++p) {
            int rowi = ldRow + p*16;
            *(float4*)(sW + rowi*AWST + ldC4) = pW[p];
            *(float4*)(sV + rowi*AVST + ldC4) = pV[p];
        }
        __syncthreads();
        if (c + 1 < SEQ/64) {
            #pragma unroll
            for (int p = 0; p < 4; ++p) {
                int rowi = ldRow + p*16;
                pW[p] = *(const float4*)(scb + ((size_t)bh*SEQ + i0 + rowi)*SEQ + (c+1)*64 + ldC4);
                pV[p] = to_tf32x4(*(const float4*)(kvb + (size_t)(b*SEQ + (c+1)*64 + rowi)*(2*DMODEL) + DMODEL + h*DHD + ldC4));
            }
        }

        #pragma unroll
        for (int ks = 0; ks < 8; ++ks) {
            unsigned af[2][4], bf[2][2];
            #pragma unroll
            for (int mt = 0; mt < 2; ++mt) {
                const float* ap = sW + (warpM*32 + mt*16 + g)*AWST + ks*8 + fb;
                af[mt][0] = __float_as_uint(ap[0]);
                af[mt][1] = __float_as_uint(ap[8*AWST]);
                af[mt][2] = __float_as_uint(ap[4]);
                af[mt][3] = __float_as_uint(ap[8*AWST + 4]);
            }
            #pragma unroll
            for (int nt = 0; nt < 2; ++nt) {
                const float* bp = sV + (ks*8 + fb)*AVST + warpN*16 + nt*8 + g;
                bf[nt][0] = __float_as_uint(bp[0]);
                bf[nt][1] = __float_as_uint(bp[4*AVST]);
            }
            #pragma unroll
            for (int mt = 0; mt < 2; ++mt)
                #pragma unroll
                for (int nt = 0; nt < 2; ++nt)
                    mma_tf32(acc[mt][nt], af[mt], bf[nt]);
        }
        __syncthreads();
    }

    #pragma unroll
    for (int mt = 0; mt < 2; ++mt) {
        int iLo = i0 + warpM*32 + mt*16 + g;
        int iHi = iLo + 8;
        float zLo = sinvb[bh*SEQ + iLo];
        float zHi = sinvb[bh*SEQ + iHi];
        #pragma unroll
        for (int nt = 0; nt < 2; ++nt) {
            int col = h*DHD + warpN*16 + nt*8 + 2*fb;
            *(float2*)(ob + (size_t)(b*SEQ + iLo)*DMODEL + col) =
                make_float2(acc[mt][nt][0]*zLo, acc[mt][nt][1]*zLo);
            *(float2*)(ob + (size_t)(b*SEQ + iHi)*DMODEL + col) =
                make_float2(acc[mt][nt][2]*zHi, acc[mt][nt][3]*zHi);
        }
    }
}

// ---------------- residual + RMSNorm (per row of 512) ----------------
__global__ __launch_bounds__(128) void rms_add_kernel(
    const float* __restrict__ x, const float* __restrict__ a,
    const float* __restrict__ w, float* __restrict__ out)
{
    __shared__ float red[4];
    int row = blockIdx.x;
    int t = threadIdx.x;
    const float4* x4 = (const float4*)(x + (size_t)row*DMODEL);
    const float4* a4 = (const float4*)(a + (size_t)row*DMODEL);
    float4 xv = x4[t], av = a4[t];
    float4 s = make_float4(xv.x+av.x, xv.y+av.y, xv.z+av.z, xv.w+av.w);
    float ss = s.x*s.x + s.y*s.y + s.z*s.z + s.w*s.w;
    ss = warpSum(ss);
    if ((t & 31) == 0) red[t >> 5] = ss;
    __syncthreads();
    float tot = red[0] + red[1] + red[2] + red[3];
    float inv = rsqrtf(tot * (1.0f/DMODEL) + 1e-6f);
    float4 wv = ((const float4*)w)[t];
    float4 o = make_float4(s.x*inv*wv.x, s.y*inv*wv.y, s.z*inv*wv.z, s.w*inv*wv.w);
    ((float4*)(out + (size_t)row*DMODEL))[t] = o;
}

// ---------------- silu(u1)*u2 ----------------
__global__ void silu_mul_kernel(const float* __restrict__ u1, const float* __restrict__ u2,
                                float* __restrict__ g, int n4)
{
    int i = blockIdx.x*blockDim.x + threadIdx.x;
    if (i < n4) {
        float4 a = ((const float4*)u1)[i];
        float4 bb = ((const float4*)u2)[i];
        float4 r;
        r.x = a.x / (1.f + __expf(-a.x)) * bb.x;
        r.y = a.y / (1.f + __expf(-a.y)) * bb.y;
        r.z = a.z / (1.f + __expf(-a.z)) * bb.z;
        r.w = a.w / (1.f + __expf(-a.w)) * bb.w;
        ((float4*)g)[i] = r;
    }
}

// ---------------- instance norm over sequence dim ----------------
__global__ __launch_bounds__(256) void in1_kernel(
    const float* __restrict__ hh, const float* __restrict__ ffn,
    float* __restrict__ y, float* __restrict__ psum, float* __restrict__ psq)
{
    int b = blockIdx.y, chunk = blockIdx.x;
    int s0 = chunk * 32;
    int t = threadIdx.x;
    float s_[2] = {0.f, 0.f}, q_[2] = {0.f, 0.f};
    for (int s = 0; s < 32; ++s) {
        size_t base = ((size_t)(b*SEQ + s0 + s))*DMODEL;
        #pragma unroll
        for (int u = 0; u < 2; ++u) {
            int d = t + u*256;
            float yv = hh[base + d] + ffn[base + d];
            y[base + d] = yv;
            s_[u] += yv; q_[u] += yv*yv;
        }
    }
    #pragma unroll
    for (int u = 0; u < 2; ++u) {
        size_t pidx = ((size_t)b*32 + chunk)*DMODEL + t + u*256;
        psum[pidx] = s_[u];
        psq [pidx] = q_[u];
    }
}

__global__ void in2_kernel(const float* __restrict__ psum, const float* __restrict__ psq,
                           float* __restrict__ mean, float* __restrict__ rstd)
{
    int b = blockIdx.x, d = threadIdx.x;
    float s = 0.f, q = 0.f;
    for (int c = 0; c < 32; ++c) {
        size_t pidx = ((size_t)b*32 + c)*DMODEL + d;
        s += psum[pidx]; q += psq[pidx];
    }
    float m = s * (1.0f/SEQ);
    float v = q * (1.0f/SEQ) - m*m;
    mean[b*DMODEL + d] = m;
    rstd[b*DMODEL + d] = rsqrtf(v + 1e-5f);
}

__global__ void in3_kernel(const float* __restrict__ y, const float* __restrict__ mean,
                           const float* __restrict__ rstd, const float* __restrict__ w,
                           const float* __restrict__ bb, float* __restrict__ out)
{
    int i = blockIdx.x*blockDim.x + threadIdx.x;
    if (i < MTOT*DMODEL) {
        int d = i & (DMODEL - 1);
        int b = i >> 19;  // SEQ*DMODEL = 2^19
        float m = mean[b*DMODEL + d], r = rstd[b*DMODEL + d];
        out[i] = (y[i] - m) * r * w[d] + bb[d];
    }
}

// ---------------- launch ----------------
extern "C" void kernel_launch(void* const* d_in, const int* in_sizes, int n_in,
                              void* d_out, int out_size)
{
    (void)in_sizes; (void)n_in; (void)out_size;
    const float* x    = (const float*)d_in[0];
    const float* Wq   = (const float*)d_in[1];
    const float* bq   = (const float*)d_in[2];
    const float* Wkv  = (const float*)d_in[3];
    const float* bkv  = (const float*)d_in[4];
    const float* Wo   = (const float*)d_in[5];
    const float* bo   = (const float*)d_in[6];
    const float* rmsw = (const float*)d_in[7];
    const float* l1   = (const float*)d_in[8];
    const float* l2   = (const float*)d_in[9];
    const float* l3   = (const float*)d_in[10];
    const float* inw  = (const float*)d_in[11];
    const float* inb  = (const float*)d_in[12];
    float* out = (float*)d_out;

    float *q, *kv, *o, *att, *hbuf, *u1, *u2, *gate, *ffn, *y, *ps, *pq, *mn, *rs, *sc, *sv;
    cudaGetSymbolAddress((void**)&q,    g_q);
    cudaGetSymbolAddress((void**)&kv,   g_kv);
    cudaGetSymbolAddress((void**)&o,    g_o);
    cudaGetSymbolAddress((void**)&att,  g_att);
    cudaGetSymbolAddress((void**)&hbuf, g_h);
    cudaGetSymbolAddress((void**)&u1,   g_u1);
    cudaGetSymbolAddress((void**)&u2,   g_u2);
    cudaGetSymbolAddress((void**)&gate, g_gate);
    cudaGetSymbolAddress((void**)&ffn,  g_ffn);
    cudaGetSymbolAddress((void**)&y,    g_y);
    cudaGetSymbolAddress((void**)&ps,   g_psum);
    cudaGetSymbolAddress((void**)&pq,   g_psq);
    cudaGetSymbolAddress((void**)&mn,   g_mean);
    cudaGetSymbolAddress((void**)&rs,   g_rstd);
    cudaGetSymbolAddress((void**)&sc,   g_sc);
    cudaGetSymbolAddress((void**)&sv,   g_sinv);

    const int gemmSmem = (2*A_BUF_F32 + 2*B_BUF_F32) * 4;   // 67584 B
    cudaFuncSetAttribute(tf32gemm_kernel, cudaFuncAttributeMaxDynamicSharedMemorySize, gemmSmem);
    const int scoresSmem = 2*128*SST*4;                      // 69632 B
    cudaFuncSetAttribute(scores_kernel, cudaFuncAttributeMaxDynamicSharedMemorySize, scoresSmem);

    // QKV projections
    tf32gemm_kernel<<<dim3(DMODEL/128,   MTOT/128), 256, gemmSmem>>>(x, Wq,  bq,  q,  MTOT, DMODEL,   DMODEL);
    tf32gemm_kernel<<<dim3(2*DMODEL/128, MTOT/128), 256, gemmSmem>>>(x, Wkv, bkv, kv, MTOT, 2*DMODEL, DMODEL);

    // sparse attention: scores -> select -> AV
    scores_kernel<<<dim3(SEQ/128, SEQ/128, BSZ*NH), 256, scoresSmem>>>(q, kv, sc);
    select_kernel<<<BSZ*NH*SEQ/8, 256>>>(sc, sv);
    av_kernel<<<dim3(SEQ/64, BSZ*NH), 256>>>(sc, kv, sv, o);

    // output projection + residual + rmsnorm
    tf32gemm_kernel<<<dim3(DMODEL/128, MTOT/128), 256, gemmSmem>>>(o, Wo, bo, att, MTOT, DMODEL, DMODEL);
    rms_add_kernel<<<MTOT, 128>>>(x, att, rmsw, hbuf);

    // SwiGLU FFN
    tf32gemm_kernel<<<dim3(INNER_DIM/128, MTOT/128), 256, gemmSmem>>>(hbuf, l1, nullptr, u1, MTOT, INNER_DIM, DMODEL);
    tf32gemm_kernel<<<dim3(INNER_DIM/128, MTOT/128), 256, gemmSmem>>>(hbuf, l2, nullptr, u2, MTOT, INNER_DIM, DMODEL);
    silu_mul_kernel<<<(MTOT*INNER_DIM/4 + 255)/256, 256>>>(u1, u2, gate, MTOT*INNER_DIM/4);
    tf32gemm_kernel<<<dim3(DMODEL/128, MTOT/128), 256, gemmSmem>>>(gate, l3, nullptr, ffn, MTOT, DMODEL, INNER_DIM);

    // instance norm over sequence
    in1_kernel<<<dim3(32, BSZ), 256>>>(hbuf, ffn, y, ps, pq);
    in2_kernel<<<BSZ, DMODEL>>>(ps, pq, mn, rs);
    in3_kernel<<<(MTOT*DMODEL + 255)/256, 256>>>(y, mn, rs, inw, inb, out);
}